// round 13
// baseline (speedup 1.0000x reference)
#include <cuda_runtime.h>
#include <cuda_bf16.h>
#include <cstdint>
#include <cstddef>

// ---------------------------------------------------------------------------
// EncoderStack B=4 T=1024 D=1024 H=16 DK=64 DF=4096, fp32 in/out.
// GEMMs + attention via mma.sync bf16 split-precision:
//   C = (Ahi|Ahi|Alo) . (Bhi|Blo|Bhi)^T over K'=3K, operands stored (hi|lo);
//   loader maps k-tile -> segment.  GEMM tile 128x256 (warp 64x64).
//   QKV GEMM epilogue emits pre-split Q/K + bf16 V (copy-only attn staging).
// ---------------------------------------------------------------------------
#define Bsz 4
#define Tn  1024
#define Dn  1024
#define Hn  16
#define DKn 64
#define DFn 4096
#define Mrows 4096

// ---- scratch (device globals; allocation-free per harness rules) ----------
__device__ __nv_bfloat16 g_A2x [Mrows * 2048];     // x  (hi|lo)
__device__ __nv_bfloat16 g_B2qkv[3072 * 2048];     // Wq|Wk|Wv^T (hi|lo)
__device__ __nv_bfloat16 g_Qspl[Mrows * 2048];     // Q/8 split
__device__ __nv_bfloat16 g_Kspl[Mrows * 2048];     // K split
__device__ __nv_bfloat16 g_Vb  [Mrows * 1024];     // V bf16
__device__ float         g_att [Mrows * Dn];
__device__ float         g_x1  [Mrows * Dn];
__device__ __nv_bfloat16 g_A2x1[Mrows * 2048];     // x1 (hi|lo)
__device__ __nv_bfloat16 g_B2w1[DFn * 2048];       // W1^T (hi|lo)
__device__ __nv_bfloat16 g_A2h [Mrows * 8192];     // relu(h1) (hi|lo)
__device__ __nv_bfloat16 g_B2w2[Dn * 8192];        // W2^T (hi|lo)
__device__ float         g_ff  [Mrows * Dn];

__device__ __forceinline__ uint32_t smem_u32(const void* p) {
    uint32_t a;
    asm("{ .reg .u64 t; cvta.to.shared.u64 t, %1; cvt.u32.u64 %0, t; }"
        : "=r"(a) : "l"(p));
    return a;
}
__device__ __forceinline__ void split2(float a, float b, uint32_t& hi, uint32_t& lo) {
    __nv_bfloat16 ha = __float2bfloat16(a), hb = __float2bfloat16(b);
    __nv_bfloat16 la = __float2bfloat16(a - __bfloat162float(ha));
    __nv_bfloat16 lb = __float2bfloat16(b - __bfloat162float(hb));
    __nv_bfloat162 H; H.x = ha; H.y = hb;
    __nv_bfloat162 L; L.x = la; L.y = lb;
    hi = *(uint32_t*)&H; lo = *(uint32_t*)&L;
}
__device__ __forceinline__ uint32_t pack_bf16(float a, float b) {
    __nv_bfloat162 t = __floats2bfloat162_rn(a, b);
    return *(uint32_t*)&t;
}

#define LDSM_X4(d, addr)                                                        \
    asm volatile("ldmatrix.sync.aligned.m8n8.x4.shared.b16 {%0,%1,%2,%3}, [%4];"\
        : "=r"((d)[0]), "=r"((d)[1]), "=r"((d)[2]), "=r"((d)[3]) : "r"(addr))
#define MMA16816(c, a0, a1, a2, a3, b0, b1)                                     \
    asm volatile("mma.sync.aligned.m16n8k16.row.col.f32.bf16.bf16.f32 "         \
        "{%0,%1,%2,%3}, {%4,%5,%6,%7}, {%8,%9}, {%0,%1,%2,%3};"                 \
        : "+f"((c)[0]), "+f"((c)[1]), "+f"((c)[2]), "+f"((c)[3])                \
        : "r"(a0), "r"(a1), "r"(a2), "r"(a3), "r"(b0), "r"(b1))

// ---------------------------------------------------------------------------
// Split-bf16 HMMA GEMM, 128x256 tile, 3-stage cp.async pipeline.
// A,B stored (hi|lo), row stride 2*Ksz. k-tile t in [0, 3*KT0):
//   seg = t/KT0;  A pattern (hi,hi,lo);  B pattern (hi,lo,hi).
// EPI 1: +bias, relu, (hi|lo) bf16 pair to C3.   EPI 2: +bias, C fp32.
// EPI 3: QKV epilogue -> qout (Q/8 split), kout (K split), vout (V bf16).
// ---------------------------------------------------------------------------
template <int EPI>
__global__ __launch_bounds__(256, 1) void gemm3_kernel(
    const __nv_bfloat16* __restrict__ A, const __nv_bfloat16* __restrict__ B,
    const float* __restrict__ bias,
    float* __restrict__ C, int ldc,
    __nv_bfloat16* __restrict__ C3, int c3stride, int c3seg,
    __nv_bfloat16* __restrict__ qout, __nv_bfloat16* __restrict__ kout,
    __nv_bfloat16* __restrict__ vout,
    int Ksz, int KT0)
{
    extern __shared__ char dynsm[];
    char* base = (char*)(((uintptr_t)dynsm + 127) & ~(uintptr_t)127);
    __shared__ float s_bias[256];

    const int tid  = threadIdx.x;
    const int wid  = tid >> 5;
    const int lane = tid & 31;
    const int bm = blockIdx.y * 128;
    const int bn = blockIdx.x * 256;
    const int K2 = 2 * Ksz;
    const int KT = 3 * KT0;

    if (EPI == 1 || EPI == 2) s_bias[tid] = bias[bn + tid];

    uint32_t sA[3], sB[3];
#pragma unroll
    for (int s = 0; s < 3; s++) {
        sA[s] = smem_u32(base + s * 49152);
        sB[s] = sA[s] + 16384;
    }

    const __nv_bfloat16* Abase = A + (size_t)bm * K2;
    const __nv_bfloat16* Bbase = B + (size_t)bn * K2;

    // A tile 128x64 (8 chunks/row), B tile 256x64: total 3072 cp.async / 256 thr
#define LOAD_STAGE(s, u)                                                        \
    do {                                                                        \
        const int _seg = ((u) >= 2 * KT0) ? 2 : (((u) >= KT0) ? 1 : 0);         \
        const int _kin = (u) - _seg * KT0;                                      \
        const __nv_bfloat16* Ag = Abase + (size_t)((_seg == 2) ? Ksz : 0)       \
                                        + (size_t)_kin * 64;                    \
        const __nv_bfloat16* Bg = Bbase + (size_t)((_seg == 1) ? Ksz : 0)       \
                                        + (size_t)_kin * 64;                    \
        _Pragma("unroll")                                                       \
        for (int i = 0; i < 4; i++) {                                           \
            int idx = tid + i * 256;                                            \
            int r = idx >> 3, ch = idx & 7;                                     \
            uint32_t off = (uint32_t)(r * 128 + ((ch ^ (r & 7)) << 4));         \
            asm volatile("cp.async.cg.shared.global [%0], [%1], 16;"            \
                :: "r"(sA[s] + off), "l"(Ag + (size_t)r * K2 + ch * 8)          \
                : "memory");                                                    \
        }                                                                       \
        _Pragma("unroll")                                                       \
        for (int i = 0; i < 8; i++) {                                           \
            int idx = tid + i * 256;                                            \
            int r = idx >> 3, ch = idx & 7;                                     \
            uint32_t off = (uint32_t)(r * 128 + ((ch ^ (r & 7)) << 4));         \
            asm volatile("cp.async.cg.shared.global [%0], [%1], 16;"            \
                :: "r"(sB[s] + off), "l"(Bg + (size_t)r * K2 + ch * 8)          \
                : "memory");                                                    \
        }                                                                       \
        asm volatile("cp.async.commit_group;" ::: "memory");                    \
    } while (0)

    const int wm = (wid >> 2) * 64;    // 0 / 64
    const int wn = (wid & 3) * 64;     // 0,64,128,192
    const int a_roff = ((lane >> 3) & 1) * 8 + (lane & 7);
    const int a_koff = lane >> 4;
    const int b_roff = ((lane >> 4) & 1) * 8 + (lane & 7);
    const int b_koff = (lane >> 3) & 1;

    float acc[4][8][4];
#pragma unroll
    for (int mt = 0; mt < 4; mt++)
#pragma unroll
        for (int nt = 0; nt < 8; nt++)
#pragma unroll
            for (int e = 0; e < 4; e++) acc[mt][nt][e] = 0.f;

    LOAD_STAGE(0, 0);
    LOAD_STAGE(1, 1);

    int sidx = 0;
    for (int t = 0; t < KT; t++) {
        if (t + 1 < KT) {
            asm volatile("cp.async.wait_group 1;" ::: "memory");
        } else {
            asm volatile("cp.async.wait_group 0;" ::: "memory");
        }
        __syncthreads();
        if (t + 2 < KT) {
            const int ns = (sidx + 2 >= 3) ? sidx - 1 : sidx + 2;
            LOAD_STAGE(ns, t + 2);
        }

        const uint32_t cA = sA[sidx], cB = sB[sidx];
#pragma unroll
        for (int ks = 0; ks < 4; ks++) {
            uint32_t af[4][4], bf2[4][4];
#pragma unroll
            for (int mt = 0; mt < 4; mt++) {
                int rA = wm + mt * 16 + a_roff;
                uint32_t addr = cA + rA * 128 +
                                ((((ks << 1) + a_koff) ^ (rA & 7)) << 4);
                LDSM_X4(af[mt], addr);
            }
#pragma unroll
            for (int p = 0; p < 4; p++) {
                int rB = wn + p * 16 + b_roff;
                uint32_t addr = cB + rB * 128 +
                                ((((ks << 1) + b_koff) ^ (rB & 7)) << 4);
                LDSM_X4(bf2[p], addr);
            }
#pragma unroll
            for (int mt = 0; mt < 4; mt++)
#pragma unroll
                for (int nt = 0; nt < 8; nt++) {
                    uint32_t b0 = bf2[nt >> 1][(nt & 1) * 2];
                    uint32_t b1 = bf2[nt >> 1][(nt & 1) * 2 + 1];
                    MMA16816(acc[mt][nt], af[mt][0], af[mt][1], af[mt][2], af[mt][3], b0, b1);
                }
        }
        __syncthreads();
        sidx = (sidx + 1 == 3) ? 0 : sidx + 1;
    }
#undef LOAD_STAGE

    const int lr = lane >> 2;
    const int lc = (lane & 3) * 2;
#pragma unroll
    for (int mt = 0; mt < 4; mt++) {
#pragma unroll
        for (int nt = 0; nt < 8; nt++) {
            float* c = acc[mt][nt];
            const int tc   = wn + nt * 8 + lc;
            const int row0 = bm + wm + mt * 16 + lr;
            if (EPI == 1) {
                float h0a = fmaxf(c[0] + s_bias[tc],     0.f);
                float h1a = fmaxf(c[1] + s_bias[tc + 1], 0.f);
                float h0b = fmaxf(c[2] + s_bias[tc],     0.f);
                float h1b = fmaxf(c[3] + s_bias[tc + 1], 0.f);
                const int nn = bn + tc;
#pragma unroll
                for (int half = 0; half < 2; half++) {
                    float v0 = half ? h0b : h0a;
                    float v1 = half ? h1b : h1a;
                    uint32_t hh, ll;
                    split2(v0, v1, hh, ll);
                    __nv_bfloat16* o = C3 + (size_t)(row0 + half * 8) * c3stride;
                    *(uint32_t*)(o + nn)         = hh;
                    *(uint32_t*)(o + c3seg + nn) = ll;
                }
            } else if (EPI == 2) {
                float2 v0 = make_float2(c[0] + s_bias[tc], c[1] + s_bias[tc + 1]);
                float2 v1 = make_float2(c[2] + s_bias[tc], c[3] + s_bias[tc + 1]);
                *(float2*)(C + (size_t)row0 * ldc + bn + tc)       = v0;
                *(float2*)(C + (size_t)(row0 + 8) * ldc + bn + tc) = v1;
            } else {  // EPI == 3 : QKV
                const int nn = bn + tc;            // 0..3071
                const int mtx = nn >> 10;          // 0 Q, 1 K, 2 V
                const int within = nn & 1023;
                const int hh = within >> 6, dd = within & 63;
                if (mtx == 0) {
#pragma unroll
                    for (int half = 0; half < 2; half++) {
                        float v0 = c[half * 2]     * 0.125f;
                        float v1 = c[half * 2 + 1] * 0.125f;
                        uint32_t hi, lo;
                        split2(v0, v1, hi, lo);
                        __nv_bfloat16* o = qout + (size_t)(row0 + half * 8) * 2048 + hh * 128 + dd;
                        *(uint32_t*)(o)      = hi;
                        *(uint32_t*)(o + 64) = lo;
                    }
                } else if (mtx == 1) {
#pragma unroll
                    for (int half = 0; half < 2; half++) {
                        uint32_t hi, lo;
                        split2(c[half * 2], c[half * 2 + 1], hi, lo);
                        __nv_bfloat16* o = kout + (size_t)(row0 + half * 8) * 2048 + hh * 128 + dd;
                        *(uint32_t*)(o)      = hi;
                        *(uint32_t*)(o + 64) = lo;
                    }
                } else {
#pragma unroll
                    for (int half = 0; half < 2; half++) {
                        __nv_bfloat16* o = vout + (size_t)(row0 + half * 8) * 1024 + hh * 64 + dd;
                        *(uint32_t*)(o) = pack_bf16(c[half * 2], c[half * 2 + 1]);
                    }
                }
            }
        }
    }
}

// ---------------------------------------------------------------------------
// HMMA flash attention; copy-only staging (validated R12 version).
// ---------------------------------------------------------------------------
__global__ __launch_bounds__(256) void attn_mma_kernel(
    const __nv_bfloat16* __restrict__ Qspl, const __nv_bfloat16* __restrict__ Kspl,
    const __nv_bfloat16* __restrict__ Vb, float* __restrict__ Og)
{
    extern __shared__ char smraw[];
    char* smp = smraw;
    const uint32_t sQ = smem_u32(smraw);
    const uint32_t sK = sQ;
    const uint32_t sV = sQ + 25600;

    const int tid = threadIdx.x;
    const int wid = tid >> 5, lane = tid & 31;
    const int bh = blockIdx.y;
    const int b = bh >> 4, h = bh & 15;
    const int q0 = blockIdx.x * 128;
    const size_t rowQ = (size_t)b * 1024;
    const __nv_bfloat16* Qb = Qspl + rowQ * 2048 + h * 128;
    const __nv_bfloat16* Kb = Kspl + rowQ * 2048 + h * 128;
    const __nv_bfloat16* Vg = Vb   + rowQ * 1024 + h * 64;
    float* Obase = Og + rowQ * Dn + h * DKn;

    const int a_roff = ((lane >> 3) & 1) * 8 + (lane & 7);
    const int a_koff = lane >> 4;
    const int b_roff = ((lane >> 4) & 1) * 8 + (lane & 7);
    const int b_koff = (lane >> 3) & 1;

    // ---- stage Q: (hi|lo|hi), 128 rows x 16 chunks
#pragma unroll
    for (int i = 0; i < 8; i++) {
        int idx = tid + i * 256;
        int r = idx >> 4, ch = idx & 15;
        uint4 v = *(const uint4*)(Qb + (size_t)(q0 + r) * 2048 + ch * 8);
        char* row = smp + r * 400;
        if (ch < 8) {
            *(uint4*)(row + ch * 16)       = v;
            *(uint4*)(row + 256 + ch * 16) = v;
        } else {
            *(uint4*)(row + 128 + (ch - 8) * 16) = v;
        }
    }
    __syncthreads();

    uint32_t qf[12][4];
#pragma unroll
    for (int kt = 0; kt < 12; kt++) {
        uint32_t addr = sQ + (wid * 16 + a_roff) * 400 + (kt * 2 + a_koff) * 16;
        LDSM_X4(qf[kt], addr);
    }
    __syncthreads();

    float m0 = -1e30f, m1 = -1e30f, l0 = 0.f, l1 = 0.f;
    float of[8][4];
#pragma unroll
    for (int j = 0; j < 8; j++)
#pragma unroll
        for (int e = 0; e < 4; e++) of[j][e] = 0.f;

    for (int kv0 = 0; kv0 < Tn; kv0 += 64) {
#pragma unroll
        for (int i = 0; i < 4; i++) {
            int idx = tid + i * 256;
            int r = idx >> 4, ch = idx & 15;
            uint4 v = *(const uint4*)(Kb + (size_t)(kv0 + r) * 2048 + ch * 8);
            char* row = smp + r * 400;
            if (ch < 8) {
                *(uint4*)(row + ch * 16)       = v;
                *(uint4*)(row + 128 + ch * 16) = v;
            } else {
                *(uint4*)(row + 256 + (ch - 8) * 16) = v;
            }
        }
#pragma unroll
        for (int i = 0; i < 2; i++) {
            int idx = tid + i * 256;
            int r = idx >> 3, ch = idx & 7;
            uint4 v = *(const uint4*)(Vg + (size_t)(kv0 + r) * 1024 + ch * 8);
            const __nv_bfloat16* pv = (const __nv_bfloat16*)&v;
            char* vb = smp + 25600 + r * 2;
#pragma unroll
            for (int j = 0; j < 8; j++)
                *(__nv_bfloat16*)(vb + (ch * 8 + j) * 144) = pv[j];
        }
        __syncthreads();

        float sf[8][4];
#pragma unroll
        for (int nt = 0; nt < 8; nt++)
#pragma unroll
            for (int e = 0; e < 4; e++) sf[nt][e] = 0.f;

#pragma unroll
        for (int kt = 0; kt < 12; kt++) {
            uint32_t bf[4][4];
#pragma unroll
            for (int p = 0; p < 4; p++) {
                uint32_t addr = sK + (p * 16 + b_roff) * 400 + (kt * 2 + b_koff) * 16;
                LDSM_X4(bf[p], addr);
            }
#pragma unroll
            for (int nt = 0; nt < 8; nt++) {
                uint32_t bb0 = bf[nt >> 1][(nt & 1) * 2];
                uint32_t bb1 = bf[nt >> 1][(nt & 1) * 2 + 1];
                MMA16816(sf[nt], qf[kt][0], qf[kt][1], qf[kt][2], qf[kt][3], bb0, bb1);
            }
        }

        float mx0 = -1e30f, mx1 = -1e30f;
#pragma unroll
        for (int nt = 0; nt < 8; nt++) {
            mx0 = fmaxf(mx0, fmaxf(sf[nt][0], sf[nt][1]));
            mx1 = fmaxf(mx1, fmaxf(sf[nt][2], sf[nt][3]));
        }
        mx0 = fmaxf(mx0, __shfl_xor_sync(0xffffffffu, mx0, 1));
        mx0 = fmaxf(mx0, __shfl_xor_sync(0xffffffffu, mx0, 2));
        mx1 = fmaxf(mx1, __shfl_xor_sync(0xffffffffu, mx1, 1));
        mx1 = fmaxf(mx1, __shfl_xor_sync(0xffffffffu, mx1, 2));
        float mn0 = fmaxf(m0, mx0), mn1 = fmaxf(m1, mx1);
        float alpha0 = __expf(m0 - mn0), alpha1 = __expf(m1 - mn1);
        m0 = mn0; m1 = mn1;
        float sum0 = 0.f, sum1 = 0.f;
#pragma unroll
        for (int nt = 0; nt < 8; nt++) {
            sf[nt][0] = __expf(sf[nt][0] - mn0);
            sf[nt][1] = __expf(sf[nt][1] - mn0);
            sf[nt][2] = __expf(sf[nt][2] - mn1);
            sf[nt][3] = __expf(sf[nt][3] - mn1);
            sum0 += sf[nt][0] + sf[nt][1];
            sum1 += sf[nt][2] + sf[nt][3];
        }
        sum0 += __shfl_xor_sync(0xffffffffu, sum0, 1);
        sum0 += __shfl_xor_sync(0xffffffffu, sum0, 2);
        sum1 += __shfl_xor_sync(0xffffffffu, sum1, 1);
        sum1 += __shfl_xor_sync(0xffffffffu, sum1, 2);
        l0 = l0 * alpha0 + sum0;
        l1 = l1 * alpha1 + sum1;
#pragma unroll
        for (int j = 0; j < 8; j++) {
            of[j][0] *= alpha0; of[j][1] *= alpha0;
            of[j][2] *= alpha1; of[j][3] *= alpha1;
        }

#pragma unroll
        for (int g = 0; g < 4; g++) {
            uint32_t a0 = pack_bf16(sf[2 * g][0],     sf[2 * g][1]);
            uint32_t a1 = pack_bf16(sf[2 * g][2],     sf[2 * g][3]);
            uint32_t a2 = pack_bf16(sf[2 * g + 1][0], sf[2 * g + 1][1]);
            uint32_t a3 = pack_bf16(sf[2 * g + 1][2], sf[2 * g + 1][3]);
            uint32_t vf[4][4];
#pragma unroll
            for (int p = 0; p < 4; p++) {
                uint32_t addr = sV + (p * 16 + b_roff) * 144 + (g * 2 + b_koff) * 16;
                LDSM_X4(vf[p], addr);
            }
#pragma unroll
            for (int j = 0; j < 8; j++) {
                uint32_t bb0 = vf[j >> 1][(j & 1) * 2];
                uint32_t bb1 = vf[j >> 1][(j & 1) * 2 + 1];
                MMA16816(of[j], a0, a1, a2, a3, bb0, bb1);
            }
        }
        __syncthreads();
    }

    const float inv0 = 1.f / l0, inv1 = 1.f / l1;
    const int r0 = q0 + wid * 16 + (lane >> 2);
    const int cc = (lane & 3) * 2;
#pragma unroll
    for (int j = 0; j < 8; j++) {
        *(float2*)(Obase + (size_t)r0 * Dn + j * 8 + cc) =
            make_float2(of[j][0] * inv0, of[j][1] * inv0);
        *(float2*)(Obase + (size_t)(r0 + 8) * Dn + j * 8 + cc) =
            make_float2(of[j][2] * inv1, of[j][3] * inv1);
    }
}

// ---------------------------------------------------------------------------
// Weight transpose + split:  W[K,N] fp32  ->  B2[N, 2K] bf16 = (hi | lo)
// ---------------------------------------------------------------------------
__global__ __launch_bounds__(256) void wtrans2_kernel(
    const float* __restrict__ W, __nv_bfloat16* __restrict__ B2,
    int K, int N, int K2)
{
    __shared__ float t[32][33];
    const int n0 = blockIdx.x * 32, k0 = blockIdx.y * 32;
    const int tx = threadIdx.x & 31, ty = threadIdx.x >> 5;
#pragma unroll
    for (int i = 0; i < 4; i++)
        t[ty + 8 * i][tx] = W[(size_t)(k0 + ty + 8 * i) * N + n0 + tx];
    __syncthreads();
#pragma unroll
    for (int i = 0; i < 4; i++) {
        int n = n0 + ty + 8 * i;
        int k = k0 + tx;
        float v = t[tx][ty + 8 * i];
        __nv_bfloat16 hi = __float2bfloat16(v);
        __nv_bfloat16 lo = __float2bfloat16(v - __bfloat162float(hi));
        __nv_bfloat16* row = B2 + (size_t)n * K2;
        row[k] = hi; row[K + k] = lo;
    }
}

// x fp32 [4096,1024] -> A2 bf16 [4096, 2048] = (hi | lo)
__global__ __launch_bounds__(256) void conv2_kernel(
    const float* __restrict__ X, __nv_bfloat16* __restrict__ A2)
{
    const int m = blockIdx.x;
    const float* xr = X + (size_t)m * Dn;
    __nv_bfloat16* ar = A2 + (size_t)m * 2048;
#pragma unroll
    for (int i = 0; i < 4; i++) {
        int k = threadIdx.x + i * 256;
        float v = xr[k];
        __nv_bfloat16 hi = __float2bfloat16(v);
        __nv_bfloat16 lo = __float2bfloat16(v - __bfloat162float(hi));
        ar[k] = hi; ar[Dn + k] = lo;
    }
}

// ---------------------------------------------------------------------------
// LayerNorm(a+b)*g+beta.  PAIR=1 also writes the (hi|lo) bf16 split.
// ---------------------------------------------------------------------------
template <int PAIR>
__global__ __launch_bounds__(256) void add_ln_kernel(
    const float* __restrict__ A, const float* __restrict__ Bv,
    const float* __restrict__ g, const float* __restrict__ beta,
    float* __restrict__ out, __nv_bfloat16* __restrict__ A2)
{
    const int row = blockIdx.x;
    const int tid = threadIdx.x;
    const float* a = A + (size_t)row * Dn;
    const float* b = Bv + (size_t)row * Dn;

    float v[4];
    float s = 0.f, s2 = 0.f;
#pragma unroll
    for (int i = 0; i < 4; i++) {
        int c = tid + i * 256;
        v[i] = a[c] + b[c];
        s += v[i];
        s2 += v[i] * v[i];
    }
#pragma unroll
    for (int off = 16; off >= 1; off >>= 1) {
        s  += __shfl_xor_sync(0xffffffffu, s,  off);
        s2 += __shfl_xor_sync(0xffffffffu, s2, off);
    }
    __shared__ float red[16];
    const int w = tid >> 5;
    if ((tid & 31) == 0) { red[w] = s; red[w + 8] = s2; }
    __syncthreads();
    float ts = 0.f, ts2 = 0.f;
#pragma unroll
    for (int i = 0; i < 8; i++) { ts += red[i]; ts2 += red[8 + i]; }
    const float mu  = ts * (1.f / Dn);
    const float var = ts2 * (1.f / Dn) - mu * mu;
    const float r = rsqrtf(var + 1e-5f);
    float* orow = out + (size_t)row * Dn;
    __nv_bfloat16* a2 = PAIR ? (A2 + (size_t)row * 2048) : nullptr;
#pragma unroll
    for (int i = 0; i < 4; i++) {
        int c = tid + i * 256;
        float y = (v[i] - mu) * r * g[c] + beta[c];
        orow[c] = y;
        if (PAIR) {
            __nv_bfloat16 hi = __float2bfloat16(y);
            __nv_bfloat16 lo = __float2bfloat16(y - __bfloat162float(hi));
            a2[c] = hi; a2[Dn + c] = lo;
        }
    }
}

// ---------------------------------------------------------------------------
extern "C" void kernel_launch(void* const* d_in, const int* in_sizes, int n_in,
                              void* d_out, int out_size)
{
    (void)in_sizes; (void)n_in; (void)out_size;
    const float* x    = (const float*)d_in[0];
    const float* Wq   = (const float*)d_in[1];
    const float* Wk   = (const float*)d_in[2];
    const float* Wv   = (const float*)d_in[3];
    const float* W1   = (const float*)d_in[4];
    const float* b1   = (const float*)d_in[5];
    const float* W2   = (const float*)d_in[6];
    const float* b2   = (const float*)d_in[7];
    const float* ln1g = (const float*)d_in[8];
    const float* ln1b = (const float*)d_in[9];
    const float* ln2g = (const float*)d_in[10];
    const float* ln2b = (const float*)d_in[11];
    float* out = (float*)d_out;

    __nv_bfloat16 *A2x, *B2qkv, *Qspl, *Kspl, *Vb, *A2x1, *B2w1, *A2h, *B2w2;
    float *att, *x1, *ff;
    cudaGetSymbolAddress((void**)&A2x,   g_A2x);
    cudaGetSymbolAddress((void**)&B2qkv, g_B2qkv);
    cudaGetSymbolAddress((void**)&Qspl,  g_Qspl);
    cudaGetSymbolAddress((void**)&Kspl,  g_Kspl);
    cudaGetSymbolAddress((void**)&Vb,    g_Vb);
    cudaGetSymbolAddress((void**)&att,   g_att);
    cudaGetSymbolAddress((void**)&x1,    g_x1);
    cudaGetSymbolAddress((void**)&A2x1,  g_A2x1);
    cudaGetSymbolAddress((void**)&B2w1,  g_B2w1);
    cudaGetSymbolAddress((void**)&A2h,   g_A2h);
    cudaGetSymbolAddress((void**)&B2w2,  g_B2w2);
    cudaGetSymbolAddress((void**)&ff,    g_ff);

    const int GEMM_SMEM = 3 * 49152 + 128;   // 3-stage 128x256 tiles (144KB)
    const int ATT_SMEM  = 51200;
    cudaFuncSetAttribute(gemm3_kernel<1>, cudaFuncAttributeMaxDynamicSharedMemorySize, GEMM_SMEM);
    cudaFuncSetAttribute(gemm3_kernel<2>, cudaFuncAttributeMaxDynamicSharedMemorySize, GEMM_SMEM);
    cudaFuncSetAttribute(gemm3_kernel<3>, cudaFuncAttributeMaxDynamicSharedMemorySize, GEMM_SMEM);
    cudaFuncSetAttribute(attn_mma_kernel, cudaFuncAttributeMaxDynamicSharedMemorySize, ATT_SMEM);

    // ---- operand prep ----
    conv2_kernel<<<Mrows, 256>>>(x, A2x);
    wtrans2_kernel<<<dim3(Dn / 32, Dn / 32), 256>>>(Wq, B2qkv,                       Dn, Dn,  2048);
    wtrans2_kernel<<<dim3(Dn / 32, Dn / 32), 256>>>(Wk, B2qkv + (size_t)1024 * 2048, Dn, Dn,  2048);
    wtrans2_kernel<<<dim3(Dn / 32, Dn / 32), 256>>>(Wv, B2qkv + (size_t)2048 * 2048, Dn, Dn,  2048);
    wtrans2_kernel<<<dim3(DFn / 32, Dn / 32), 256>>>(W1, B2w1,                       Dn, DFn, 2048);

    // ---- QKV = x @ [Wq|Wk|Wv], epilogue -> pre-split Q/K + bf16 V ----
    gemm3_kernel<3><<<dim3(3072 / 256, Mrows / 128), 256, GEMM_SMEM>>>(
        A2x, B2qkv, nullptr, nullptr, 0, nullptr, 0, 0, Qspl, Kspl, Vb, Dn, Dn / 64);

    wtrans2_kernel<<<dim3(Dn / 32, DFn / 32), 256>>>(W2, B2w2, DFn, Dn, 8192);

    // ---- attention (HMMA, copy-only staging) ----
    attn_mma_kernel<<<dim3(Tn / 128, Bsz * Hn), 256, ATT_SMEM>>>(
        Qspl, Kspl, Vb, att);

    // ---- x1 = LN(x + att)  (+ (hi|lo) split for FFN1) ----
    add_ln_kernel<1><<<Mrows, 256>>>(x, att, ln1g, ln1b, x1, A2x1);

    // ---- h1 = relu(x1 @ W1 + b1) -> bf16 (hi|lo) ----
    gemm3_kernel<1><<<dim3(DFn / 256, Mrows / 128), 256, GEMM_SMEM>>>(
        A2x1, B2w1, b1, nullptr, 0, A2h, 8192, DFn, nullptr, nullptr, nullptr, Dn, Dn / 64);

    // ---- ff = h1 @ W2 + b2 ----
    gemm3_kernel<2><<<dim3(Dn / 256, Mrows / 128), 256, GEMM_SMEM>>>(
        A2h, B2w2, b2, ff, Dn, nullptr, 0, 0, nullptr, nullptr, nullptr, DFn, DFn / 64);

    // ---- out = LN(x1 + ff) ----
    add_ln_kernel<0><<<Mrows, 256>>>(x1, ff, ln2g, ln2b, out, nullptr);
}

// round 14
// speedup vs baseline: 1.1187x; 1.1187x over previous
#include <cuda_runtime.h>
#include <cuda_bf16.h>
#include <cuda_fp16.h>
#include <cstdint>
#include <cstddef>

// ---------------------------------------------------------------------------
// EncoderStack B=4 T=1024 D=1024 H=16 DK=64 DF=4096, fp32 in/out.
// GEMMs + attention via mma.sync bf16 split-precision:
//   C = (Ahi|Ahi|Alo) . (Bhi|Blo|Bhi)^T over K'=3K, operands stored (hi|lo);
//   loader maps k-tile -> segment.  Attention softmax via f16x2 ex2 (half the
//   MUFU ops), PV in f16, row-sums via ones-column mma.
// ---------------------------------------------------------------------------
#define Bsz 4
#define Tn  1024
#define Dn  1024
#define Hn  16
#define DKn 64
#define DFn 4096
#define Mrows 4096
#define LDQKV 3072

// ---- scratch (device globals; allocation-free per harness rules) ----------
__device__ __nv_bfloat16 g_A2x [Mrows * 2048];     // x  (hi|lo)
__device__ __nv_bfloat16 g_B2qkv[3072 * 2048];     // Wq|Wk|Wv^T (hi|lo)
__device__ float         g_QKV [Mrows * 3072];
__device__ float         g_att [Mrows * Dn];
__device__ float         g_x1  [Mrows * Dn];
__device__ __nv_bfloat16 g_A2x1[Mrows * 2048];     // x1 (hi|lo)
__device__ __nv_bfloat16 g_B2w1[DFn * 2048];       // W1^T (hi|lo)
__device__ __nv_bfloat16 g_A2h [Mrows * 8192];     // relu(h1) (hi|lo)
__device__ __nv_bfloat16 g_B2w2[Dn * 8192];        // W2^T (hi|lo)
__device__ float         g_ff  [Mrows * Dn];

__device__ __forceinline__ uint32_t smem_u32(const void* p) {
    uint32_t a;
    asm("{ .reg .u64 t; cvta.to.shared.u64 t, %1; cvt.u32.u64 %0, t; }"
        : "=r"(a) : "l"(p));
    return a;
}
__device__ __forceinline__ void split2(float a, float b, uint32_t& hi, uint32_t& lo) {
    __nv_bfloat16 ha = __float2bfloat16(a), hb = __float2bfloat16(b);
    __nv_bfloat16 la = __float2bfloat16(a - __bfloat162float(ha));
    __nv_bfloat16 lb = __float2bfloat16(b - __bfloat162float(hb));
    __nv_bfloat162 H; H.x = ha; H.y = hb;
    __nv_bfloat162 L; L.x = la; L.y = lb;
    hi = *(uint32_t*)&H; lo = *(uint32_t*)&L;
}

#define LDSM_X4(d, addr)                                                        \
    asm volatile("ldmatrix.sync.aligned.m8n8.x4.shared.b16 {%0,%1,%2,%3}, [%4];"\
        : "=r"((d)[0]), "=r"((d)[1]), "=r"((d)[2]), "=r"((d)[3]) : "r"(addr))
#define MMA16816(c, a0, a1, a2, a3, b0, b1)                                     \
    asm volatile("mma.sync.aligned.m16n8k16.row.col.f32.bf16.bf16.f32 "         \
        "{%0,%1,%2,%3}, {%4,%5,%6,%7}, {%8,%9}, {%0,%1,%2,%3};"                 \
        : "+f"((c)[0]), "+f"((c)[1]), "+f"((c)[2]), "+f"((c)[3])                \
        : "r"(a0), "r"(a1), "r"(a2), "r"(a3), "r"(b0), "r"(b1))
#define MMA16816F16(c, a0, a1, a2, a3, b0, b1)                                  \
    asm volatile("mma.sync.aligned.m16n8k16.row.col.f32.f16.f16.f32 "           \
        "{%0,%1,%2,%3}, {%4,%5,%6,%7}, {%8,%9}, {%0,%1,%2,%3};"                 \
        : "+f"((c)[0]), "+f"((c)[1]), "+f"((c)[2]), "+f"((c)[3])                \
        : "r"(a0), "r"(a1), "r"(a2), "r"(a3), "r"(b0), "r"(b1))

// ---------------------------------------------------------------------------
// Split-bf16 HMMA GEMM, 3-stage cp.async pipeline, one barrier per k-tile.
// A,B stored (hi|lo), row stride 2*Ksz. k-tile t in [0, 3*KT0):
//   seg = t/KT0;  A pattern (hi,hi,lo);  B pattern (hi,lo,hi).
// EPI 0: C fp32.  EPI 1: +bias, relu, (hi|lo) bf16 pair to C3.  EPI 2: +bias.
// ---------------------------------------------------------------------------
template <int EPI>
__global__ __launch_bounds__(256) void gemm3_kernel(
    const __nv_bfloat16* __restrict__ A, const __nv_bfloat16* __restrict__ B,
    const float* __restrict__ bias,
    float* __restrict__ C, int ldc,
    __nv_bfloat16* __restrict__ C3, int c3stride, int c3seg,
    int Ksz, int KT0)
{
    extern __shared__ char dynsm[];
    char* base = (char*)(((uintptr_t)dynsm + 127) & ~(uintptr_t)127);
    __shared__ float s_bias[128];

    const int tid  = threadIdx.x;
    const int wid  = tid >> 5;
    const int lane = tid & 31;
    const int bm = blockIdx.y * 128;
    const int bn = blockIdx.x * 128;
    const int K2 = 2 * Ksz;
    const int KT = 3 * KT0;

    if (EPI > 0 && tid < 128) s_bias[tid] = bias[bn + tid];

    uint32_t sA[3], sB[3];
#pragma unroll
    for (int s = 0; s < 3; s++) {
        sA[s] = smem_u32(base + s * 32768);
        sB[s] = sA[s] + 16384;
    }

    const __nv_bfloat16* Abase = A + (size_t)bm * K2;
    const __nv_bfloat16* Bbase = B + (size_t)bn * K2;

#define LOAD_STAGE(s, u)                                                        \
    do {                                                                        \
        const int _seg = ((u) >= 2 * KT0) ? 2 : (((u) >= KT0) ? 1 : 0);         \
        const int _kin = (u) - _seg * KT0;                                      \
        const __nv_bfloat16* Ag = Abase + (size_t)((_seg == 2) ? Ksz : 0)       \
                                        + (size_t)_kin * 64;                    \
        const __nv_bfloat16* Bg = Bbase + (size_t)((_seg == 1) ? Ksz : 0)       \
                                        + (size_t)_kin * 64;                    \
        _Pragma("unroll")                                                       \
        for (int i = 0; i < 4; i++) {                                           \
            int idx = tid + i * 256;                                            \
            int r = idx >> 3, ch = idx & 7;                                     \
            uint32_t off = (uint32_t)(r * 128 + ((ch ^ (r & 7)) << 4));         \
            asm volatile("cp.async.cg.shared.global [%0], [%1], 16;"            \
                :: "r"(sA[s] + off), "l"(Ag + (size_t)r * K2 + ch * 8)          \
                : "memory");                                                    \
            asm volatile("cp.async.cg.shared.global [%0], [%1], 16;"            \
                :: "r"(sB[s] + off), "l"(Bg + (size_t)r * K2 + ch * 8)          \
                : "memory");                                                    \
        }                                                                       \
        asm volatile("cp.async.commit_group;" ::: "memory");                    \
    } while (0)

    const int wm = (wid >> 2) * 64;
    const int wn = (wid & 3) * 32;
    const int a_roff = ((lane >> 3) & 1) * 8 + (lane & 7);
    const int a_koff = lane >> 4;
    const int b_roff = ((lane >> 4) & 1) * 8 + (lane & 7);
    const int b_koff = (lane >> 3) & 1;

    float acc[4][4][4];
#pragma unroll
    for (int mt = 0; mt < 4; mt++)
#pragma unroll
        for (int nt = 0; nt < 4; nt++)
#pragma unroll
            for (int e = 0; e < 4; e++) acc[mt][nt][e] = 0.f;

    LOAD_STAGE(0, 0);
    LOAD_STAGE(1, 1);

    int sidx = 0;
    for (int t = 0; t < KT; t++) {
        if (t + 1 < KT) {
            asm volatile("cp.async.wait_group 1;" ::: "memory");
        } else {
            asm volatile("cp.async.wait_group 0;" ::: "memory");
        }
        __syncthreads();   // tile t visible; prior iteration's reads complete
        if (t + 2 < KT) {
            const int ns = (sidx + 2 >= 3) ? sidx - 1 : sidx + 2;
            LOAD_STAGE(ns, t + 2);
        }

        const uint32_t cA = sA[sidx], cB = sB[sidx];
#pragma unroll
        for (int ks = 0; ks < 4; ks++) {
            uint32_t af[4][4], bf2[2][4];
#pragma unroll
            for (int mt = 0; mt < 4; mt++) {
                int rA = wm + mt * 16 + a_roff;
                uint32_t addr = cA + rA * 128 +
                                ((((ks << 1) + a_koff) ^ (rA & 7)) << 4);
                LDSM_X4(af[mt], addr);
            }
#pragma unroll
            for (int p = 0; p < 2; p++) {
                int rB = wn + p * 16 + b_roff;
                uint32_t addr = cB + rB * 128 +
                                ((((ks << 1) + b_koff) ^ (rB & 7)) << 4);
                LDSM_X4(bf2[p], addr);
            }
#pragma unroll
            for (int mt = 0; mt < 4; mt++)
#pragma unroll
                for (int nt = 0; nt < 4; nt++) {
                    uint32_t b0 = bf2[nt >> 1][(nt & 1) * 2];
                    uint32_t b1 = bf2[nt >> 1][(nt & 1) * 2 + 1];
                    MMA16816(acc[mt][nt], af[mt][0], af[mt][1], af[mt][2], af[mt][3], b0, b1);
                }
        }
        // (no trailing barrier: next iteration's top barrier orders reuse)
        sidx = (sidx + 1 == 3) ? 0 : sidx + 1;
    }
#undef LOAD_STAGE

    const int lr = lane >> 2;
    const int lc = (lane & 3) * 2;
#pragma unroll
    for (int mt = 0; mt < 4; mt++) {
#pragma unroll
        for (int nt = 0; nt < 4; nt++) {
            float* c = acc[mt][nt];
            const int tc   = wn + nt * 8 + lc;
            const int row0 = bm + wm + mt * 16 + lr;
            if (EPI == 1) {
                float h0a = fmaxf(c[0] + s_bias[tc],     0.f);
                float h1a = fmaxf(c[1] + s_bias[tc + 1], 0.f);
                float h0b = fmaxf(c[2] + s_bias[tc],     0.f);
                float h1b = fmaxf(c[3] + s_bias[tc + 1], 0.f);
                const int nn = bn + tc;
#pragma unroll
                for (int half = 0; half < 2; half++) {
                    float v0 = half ? h0b : h0a;
                    float v1 = half ? h1b : h1a;
                    uint32_t hh, ll;
                    split2(v0, v1, hh, ll);
                    __nv_bfloat16* o = C3 + (size_t)(row0 + half * 8) * c3stride;
                    *(uint32_t*)(o + nn)         = hh;
                    *(uint32_t*)(o + c3seg + nn) = ll;
                }
            } else {
                float b0v = (EPI == 2) ? s_bias[tc]     : 0.f;
                float b1v = (EPI == 2) ? s_bias[tc + 1] : 0.f;
                float2 v0 = make_float2(c[0] + b0v, c[1] + b1v);
                float2 v1 = make_float2(c[2] + b0v, c[3] + b1v);
                *(float2*)(C + (size_t)row0 * ldc + bn + tc)       = v0;
                *(float2*)(C + (size_t)(row0 + 8) * ldc + bn + tc) = v1;
            }
        }
    }
}

// ---------------------------------------------------------------------------
// HMMA flash attention.  S = split-bf16 QK^T; softmax via f16x2 ex2 (2 scores
// per MUFU op); P,V in f16; PV + row-sum (ones column) on tensor cores.
// smem: Q phase 128x400B = 51200; loop: K 64x400B (25600) + Vt(f16) 64x144B.
// ---------------------------------------------------------------------------
__global__ __launch_bounds__(256) void attn_mma_kernel(
    const float* __restrict__ Qg, const float* __restrict__ Kg,
    const float* __restrict__ Vg, float* __restrict__ Og)
{
    extern __shared__ char smraw[];
    char* smp = smraw;
    const uint32_t sQ = smem_u32(smraw);
    const uint32_t sK = sQ;
    const uint32_t sV = sQ + 25600;

    const int tid = threadIdx.x;
    const int wid = tid >> 5, lane = tid & 31;
    const int bh = blockIdx.y;
    const int b = bh >> 4, h = bh & 15;
    const int q0 = blockIdx.x * 128;
    const float* Qbase = Qg + (size_t)b * Tn * LDQKV + h * DKn;
    const float* Kbase = Kg + (size_t)b * Tn * LDQKV + h * DKn;
    const float* Vbase = Vg + (size_t)b * Tn * LDQKV + h * DKn;
    float* Obase = Og + (size_t)b * Tn * Dn + h * DKn;

    const int a_roff = ((lane >> 3) & 1) * 8 + (lane & 7);
    const int a_koff = lane >> 4;
    const int b_roff = ((lane >> 4) & 1) * 8 + (lane & 7);
    const int b_koff = (lane >> 3) & 1;

    // ---- stage Q split (scaled by 1/8): (hi|hi|lo), 400B rows
#pragma unroll
    for (int i = 0; i < 8; i++) {
        int idx = tid + i * 256;
        int r = idx >> 4, c4 = (idx & 15) * 4;
        float4 q = *(const float4*)(Qbase + (size_t)(q0 + r) * LDQKV + c4);
        q.x *= 0.125f; q.y *= 0.125f; q.z *= 0.125f; q.w *= 0.125f;
        uint32_t h0, l0, h1, l1;
        split2(q.x, q.y, h0, l0);
        split2(q.z, q.w, h1, l1);
        char* row = smp + r * 400;
        *(uint2*)(row + c4 * 2)         = make_uint2(h0, h1);
        *(uint2*)(row + (64 + c4) * 2)  = make_uint2(h0, h1);
        *(uint2*)(row + (128 + c4) * 2) = make_uint2(l0, l1);
    }
    __syncthreads();

    uint32_t qf[12][4];
#pragma unroll
    for (int kt = 0; kt < 12; kt++) {
        uint32_t addr = sQ + (wid * 16 + a_roff) * 400 + (kt * 2 + a_koff) * 16;
        LDSM_X4(qf[kt], addr);
    }
    __syncthreads();

    float m0 = -1e30f, m1 = -1e30f;
    float of[8][4], osum[4];
#pragma unroll
    for (int j = 0; j < 8; j++)
#pragma unroll
        for (int e = 0; e < 4; e++) of[j][e] = 0.f;
#pragma unroll
    for (int e = 0; e < 4; e++) osum[e] = 0.f;

    const uint32_t ONES_H2 = 0x3C003C00u;   // f16 (1.0, 1.0)
    const float L2E = 1.4426950408889634f;

    for (int kv0 = 0; kv0 < Tn; kv0 += 64) {
        // ---- stage K split (hi|lo|hi) + V transposed f16
#pragma unroll
        for (int i = 0; i < 4; i++) {
            int idx = tid + i * 256;
            int r = idx >> 4, c4 = (idx & 15) * 4;
            float4 k = *(const float4*)(Kbase + (size_t)(kv0 + r) * LDQKV + c4);
            uint32_t h0, lo0, h1, lo1;
            split2(k.x, k.y, h0, lo0);
            split2(k.z, k.w, h1, lo1);
            char* row = smp + r * 400;
            *(uint2*)(row + c4 * 2)         = make_uint2(h0, h1);
            *(uint2*)(row + (64 + c4) * 2)  = make_uint2(lo0, lo1);
            *(uint2*)(row + (128 + c4) * 2) = make_uint2(h0, h1);

            float4 v = *(const float4*)(Vbase + (size_t)(kv0 + r) * LDQKV + c4);
            char* vb = smp + 25600 + r * 2;
            *(__half*)(vb + (c4 + 0) * 144) = __float2half(v.x);
            *(__half*)(vb + (c4 + 1) * 144) = __float2half(v.y);
            *(__half*)(vb + (c4 + 2) * 144) = __float2half(v.z);
            *(__half*)(vb + (c4 + 3) * 144) = __float2half(v.w);
        }
        __syncthreads();

        // ---- S = Q' . K'^T
        float sf[8][4];
#pragma unroll
        for (int nt = 0; nt < 8; nt++)
#pragma unroll
            for (int e = 0; e < 4; e++) sf[nt][e] = 0.f;

#pragma unroll
        for (int kt = 0; kt < 12; kt++) {
            uint32_t bf[4][4];
#pragma unroll
            for (int p = 0; p < 4; p++) {
                uint32_t addr = sK + (p * 16 + b_roff) * 400 + (kt * 2 + b_koff) * 16;
                LDSM_X4(bf[p], addr);
            }
#pragma unroll
            for (int nt = 0; nt < 8; nt++) {
                uint32_t bb0 = bf[nt >> 1][(nt & 1) * 2];
                uint32_t bb1 = bf[nt >> 1][(nt & 1) * 2 + 1];
                MMA16816(sf[nt], qf[kt][0], qf[kt][1], qf[kt][2], qf[kt][3], bb0, bb1);
            }
        }

        // ---- online max
        float mx0 = -1e30f, mx1 = -1e30f;
#pragma unroll
        for (int nt = 0; nt < 8; nt++) {
            mx0 = fmaxf(mx0, fmaxf(sf[nt][0], sf[nt][1]));
            mx1 = fmaxf(mx1, fmaxf(sf[nt][2], sf[nt][3]));
        }
        mx0 = fmaxf(mx0, __shfl_xor_sync(0xffffffffu, mx0, 1));
        mx0 = fmaxf(mx0, __shfl_xor_sync(0xffffffffu, mx0, 2));
        mx1 = fmaxf(mx1, __shfl_xor_sync(0xffffffffu, mx1, 1));
        mx1 = fmaxf(mx1, __shfl_xor_sync(0xffffffffu, mx1, 2));
        float mn0 = fmaxf(m0, mx0), mn1 = fmaxf(m1, mx1);
        float alpha0 = __expf(m0 - mn0), alpha1 = __expf(m1 - mn1);
        m0 = mn0; m1 = mn1;

        // ---- p = exp2((s - m) * log2e) in f16x2 (2 scores per MUFU op)
        const float nb0 = mn0 * L2E, nb1 = mn1 * L2E;
        uint32_t hp[8][2];
#pragma unroll
        for (int nt = 0; nt < 8; nt++) {
            float t0 = fmaf(sf[nt][0], L2E, -nb0);
            float t1 = fmaf(sf[nt][1], L2E, -nb0);
            float t2 = fmaf(sf[nt][2], L2E, -nb1);
            float t3 = fmaf(sf[nt][3], L2E, -nb1);
            __half2 h01 = h2exp2(__floats2half2_rn(t0, t1));
            __half2 h23 = h2exp2(__floats2half2_rn(t2, t3));
            hp[nt][0] = *(uint32_t*)&h01;
            hp[nt][1] = *(uint32_t*)&h23;
        }

        // ---- rescale running outputs
#pragma unroll
        for (int j = 0; j < 8; j++) {
            of[j][0] *= alpha0; of[j][1] *= alpha0;
            of[j][2] *= alpha1; of[j][3] *= alpha1;
        }
        osum[0] *= alpha0; osum[1] *= alpha0;
        osum[2] *= alpha1; osum[3] *= alpha1;

        // ---- O += P @ V (f16) ; row-sum via ones column
#pragma unroll
        for (int g = 0; g < 4; g++) {
            uint32_t a0 = hp[2 * g][0];
            uint32_t a1 = hp[2 * g][1];
            uint32_t a2 = hp[2 * g + 1][0];
            uint32_t a3 = hp[2 * g + 1][1];
            uint32_t vf[4][4];
#pragma unroll
            for (int p = 0; p < 4; p++) {
                uint32_t addr = sV + (p * 16 + b_roff) * 144 + (g * 2 + b_koff) * 16;
                LDSM_X4(vf[p], addr);
            }
#pragma unroll
            for (int j = 0; j < 8; j++) {
                uint32_t bb0 = vf[j >> 1][(j & 1) * 2];
                uint32_t bb1 = vf[j >> 1][(j & 1) * 2 + 1];
                MMA16816F16(of[j], a0, a1, a2, a3, bb0, bb1);
            }
            MMA16816F16(osum, a0, a1, a2, a3, ONES_H2, ONES_H2);
        }
        __syncthreads();
    }

    // ---- write O (normalized)
    const float inv0 = 1.f / osum[0], inv1 = 1.f / osum[2];
    const int r0 = q0 + wid * 16 + (lane >> 2);
    const int cc = (lane & 3) * 2;
#pragma unroll
    for (int j = 0; j < 8; j++) {
        *(float2*)(Obase + (size_t)r0 * Dn + j * 8 + cc) =
            make_float2(of[j][0] * inv0, of[j][1] * inv0);
        *(float2*)(Obase + (size_t)(r0 + 8) * Dn + j * 8 + cc) =
            make_float2(of[j][2] * inv1, of[j][3] * inv1);
    }
}

// ---------------------------------------------------------------------------
// Weight transpose + split:  W[K,N] fp32  ->  B2[N, 2K] bf16 = (hi | lo)
// ---------------------------------------------------------------------------
__global__ __launch_bounds__(256) void wtrans2_kernel(
    const float* __restrict__ W, __nv_bfloat16* __restrict__ B2,
    int K, int N, int K2)
{
    __shared__ float t[32][33];
    const int n0 = blockIdx.x * 32, k0 = blockIdx.y * 32;
    const int tx = threadIdx.x & 31, ty = threadIdx.x >> 5;
#pragma unroll
    for (int i = 0; i < 4; i++)
        t[ty + 8 * i][tx] = W[(size_t)(k0 + ty + 8 * i) * N + n0 + tx];
    __syncthreads();
#pragma unroll
    for (int i = 0; i < 4; i++) {
        int n = n0 + ty + 8 * i;
        int k = k0 + tx;
        float v = t[tx][ty + 8 * i];
        __nv_bfloat16 hi = __float2bfloat16(v);
        __nv_bfloat16 lo = __float2bfloat16(v - __bfloat162float(hi));
        __nv_bfloat16* row = B2 + (size_t)n * K2;
        row[k] = hi; row[K + k] = lo;
    }
}

// x fp32 [4096,1024] -> A2 bf16 [4096, 2048] = (hi | lo)
__global__ __launch_bounds__(256) void conv2_kernel(
    const float* __restrict__ X, __nv_bfloat16* __restrict__ A2)
{
    const int m = blockIdx.x;
    const float* xr = X + (size_t)m * Dn;
    __nv_bfloat16* ar = A2 + (size_t)m * 2048;
#pragma unroll
    for (int i = 0; i < 4; i++) {
        int k = threadIdx.x + i * 256;
        float v = xr[k];
        __nv_bfloat16 hi = __float2bfloat16(v);
        __nv_bfloat16 lo = __float2bfloat16(v - __bfloat162float(hi));
        ar[k] = hi; ar[Dn + k] = lo;
    }
}

// ---------------------------------------------------------------------------
// LayerNorm(a+b)*g+beta.  PAIR=1 also writes the (hi|lo) bf16 split.
// ---------------------------------------------------------------------------
template <int PAIR>
__global__ __launch_bounds__(256) void add_ln_kernel(
    const float* __restrict__ A, const float* __restrict__ Bv,
    const float* __restrict__ g, const float* __restrict__ beta,
    float* __restrict__ out, __nv_bfloat16* __restrict__ A2)
{
    const int row = blockIdx.x;
    const int tid = threadIdx.x;
    const float* a = A + (size_t)row * Dn;
    const float* b = Bv + (size_t)row * Dn;

    float v[4];
    float s = 0.f, s2 = 0.f;
#pragma unroll
    for (int i = 0; i < 4; i++) {
        int c = tid + i * 256;
        v[i] = a[c] + b[c];
        s += v[i];
        s2 += v[i] * v[i];
    }
#pragma unroll
    for (int off = 16; off >= 1; off >>= 1) {
        s  += __shfl_xor_sync(0xffffffffu, s,  off);
        s2 += __shfl_xor_sync(0xffffffffu, s2, off);
    }
    __shared__ float red[16];
    const int w = tid >> 5;
    if ((tid & 31) == 0) { red[w] = s; red[w + 8] = s2; }
    __syncthreads();
    float ts = 0.f, ts2 = 0.f;
#pragma unroll
    for (int i = 0; i < 8; i++) { ts += red[i]; ts2 += red[8 + i]; }
    const float mu  = ts * (1.f / Dn);
    const float var = ts2 * (1.f / Dn) - mu * mu;
    const float r = rsqrtf(var + 1e-5f);
    float* orow = out + (size_t)row * Dn;
    __nv_bfloat16* a2 = PAIR ? (A2 + (size_t)row * 2048) : nullptr;
#pragma unroll
    for (int i = 0; i < 4; i++) {
        int c = tid + i * 256;
        float y = (v[i] - mu) * r * g[c] + beta[c];
        orow[c] = y;
        if (PAIR) {
            __nv_bfloat16 hi = __float2bfloat16(y);
            __nv_bfloat16 lo = __float2bfloat16(y - __bfloat162float(hi));
            a2[c] = hi; a2[Dn + c] = lo;
        }
    }
}

// ---------------------------------------------------------------------------
extern "C" void kernel_launch(void* const* d_in, const int* in_sizes, int n_in,
                              void* d_out, int out_size)
{
    (void)in_sizes; (void)n_in; (void)out_size;
    const float* x    = (const float*)d_in[0];
    const float* Wq   = (const float*)d_in[1];
    const float* Wk   = (const float*)d_in[2];
    const float* Wv   = (const float*)d_in[3];
    const float* W1   = (const float*)d_in[4];
    const float* b1   = (const float*)d_in[5];
    const float* W2   = (const float*)d_in[6];
    const float* b2   = (const float*)d_in[7];
    const float* ln1g = (const float*)d_in[8];
    const float* ln1b = (const float*)d_in[9];
    const float* ln2g = (const float*)d_in[10];
    const float* ln2b = (const float*)d_in[11];
    float* out = (float*)d_out;

    __nv_bfloat16 *A2x, *B2qkv, *A2x1, *B2w1, *A2h, *B2w2;
    float *QKV, *att, *x1, *ff;
    cudaGetSymbolAddress((void**)&A2x,   g_A2x);
    cudaGetSymbolAddress((void**)&B2qkv, g_B2qkv);
    cudaGetSymbolAddress((void**)&QKV,   g_QKV);
    cudaGetSymbolAddress((void**)&att,   g_att);
    cudaGetSymbolAddress((void**)&x1,    g_x1);
    cudaGetSymbolAddress((void**)&A2x1,  g_A2x1);
    cudaGetSymbolAddress((void**)&B2w1,  g_B2w1);
    cudaGetSymbolAddress((void**)&A2h,   g_A2h);
    cudaGetSymbolAddress((void**)&B2w2,  g_B2w2);
    cudaGetSymbolAddress((void**)&ff,    g_ff);

    const int GEMM_SMEM = 3 * 32768 + 128;
    const int ATT_SMEM  = 51200;
    cudaFuncSetAttribute(gemm3_kernel<0>, cudaFuncAttributeMaxDynamicSharedMemorySize, GEMM_SMEM);
    cudaFuncSetAttribute(gemm3_kernel<1>, cudaFuncAttributeMaxDynamicSharedMemorySize, GEMM_SMEM);
    cudaFuncSetAttribute(gemm3_kernel<2>, cudaFuncAttributeMaxDynamicSharedMemorySize, GEMM_SMEM);
    cudaFuncSetAttribute(attn_mma_kernel, cudaFuncAttributeMaxDynamicSharedMemorySize, ATT_SMEM);

    // ---- operand prep (split + transpose) ----
    conv2_kernel<<<Mrows, 256>>>(x, A2x);
    wtrans2_kernel<<<dim3(Dn / 32, Dn / 32), 256>>>(Wq, B2qkv,                       Dn, Dn,  2048);
    wtrans2_kernel<<<dim3(Dn / 32, Dn / 32), 256>>>(Wk, B2qkv + (size_t)1024 * 2048, Dn, Dn,  2048);
    wtrans2_kernel<<<dim3(Dn / 32, Dn / 32), 256>>>(Wv, B2qkv + (size_t)2048 * 2048, Dn, Dn,  2048);
    wtrans2_kernel<<<dim3(DFn / 32, Dn / 32), 256>>>(W1, B2w1,                       Dn, DFn, 2048);
    wtrans2_kernel<<<dim3(Dn / 32, DFn / 32), 256>>>(W2, B2w2,                       DFn, Dn, 8192);

    // ---- QKV = x @ [Wq|Wk|Wv]  (M=4096, N=3072, K=1024) ----
    gemm3_kernel<0><<<dim3(3072 / 128, Mrows / 128), 256, GEMM_SMEM>>>(
        A2x, B2qkv, nullptr, QKV, 3072, nullptr, 0, 0, Dn, Dn / 64);

    // ---- attention (HMMA, f16 softmax/PV) ----
    attn_mma_kernel<<<dim3(Tn / 128, Bsz * Hn), 256, ATT_SMEM>>>(
        QKV, QKV + 1024, QKV + 2048, att);

    // ---- x1 = LN(x + att)  (+ (hi|lo) split for FFN1) ----
    add_ln_kernel<1><<<Mrows, 256>>>(x, att, ln1g, ln1b, x1, A2x1);

    // ---- h1 = relu(x1 @ W1 + b1) -> bf16 (hi|lo)  (K=1024) ----
    gemm3_kernel<1><<<dim3(DFn / 128, Mrows / 128), 256, GEMM_SMEM>>>(
        A2x1, B2w1, b1, nullptr, 0, A2h, 8192, DFn, Dn, Dn / 64);

    // ---- ff = h1 @ W2 + b2  (K=4096) ----
    gemm3_kernel<2><<<dim3(Dn / 128, Mrows / 128), 256, GEMM_SMEM>>>(
        A2h, B2w2, b2, ff, Dn, nullptr, 0, 0, DFn, DFn / 64);

    // ---- out = LN(x1 + ff) ----
    add_ln_kernel<0><<<Mrows, 256>>>(x1, ff, ln2g, ln2b, out, nullptr);
}

// round 15
// speedup vs baseline: 1.1234x; 1.0042x over previous
#include <cuda_runtime.h>
#include <cuda_bf16.h>
#include <cuda_fp16.h>
#include <cstdint>
#include <cstddef>

// ---------------------------------------------------------------------------
// EncoderStack B=4 T=1024 D=1024 H=16 DK=64 DF=4096, fp32 in/out.
// GEMMs + attention via mma.sync bf16 split-precision (K'=3K, segment-mapped
// (hi|lo) storage).  Attention: f16x2 ex2 softmax, f16 PV, ones-column sums,
// dedup smem (hi stored once, per-k-tile offset table).  W1/W2 transposes
// overlap the QKV GEMM + attention on a side stream.
// ---------------------------------------------------------------------------
#define Bsz 4
#define Tn  1024
#define Dn  1024
#define Hn  16
#define DKn 64
#define DFn 4096
#define Mrows 4096
#define LDQKV 3072

// ---- scratch (device globals; allocation-free per harness rules) ----------
__device__ __nv_bfloat16 g_A2x [Mrows * 2048];     // x  (hi|lo)
__device__ __nv_bfloat16 g_B2qkv[3072 * 2048];     // Wq|Wk|Wv^T (hi|lo)
__device__ float         g_QKV [Mrows * 3072];
__device__ float         g_att [Mrows * Dn];
__device__ float         g_x1  [Mrows * Dn];
__device__ __nv_bfloat16 g_A2x1[Mrows * 2048];     // x1 (hi|lo)
__device__ __nv_bfloat16 g_B2w1[DFn * 2048];       // W1^T (hi|lo)
__device__ __nv_bfloat16 g_A2h [Mrows * 8192];     // relu(h1) (hi|lo)
__device__ __nv_bfloat16 g_B2w2[Dn * 8192];        // W2^T (hi|lo)
__device__ float         g_ff  [Mrows * Dn];

__device__ __forceinline__ uint32_t smem_u32(const void* p) {
    uint32_t a;
    asm("{ .reg .u64 t; cvta.to.shared.u64 t, %1; cvt.u32.u64 %0, t; }"
        : "=r"(a) : "l"(p));
    return a;
}
__device__ __forceinline__ void split2(float a, float b, uint32_t& hi, uint32_t& lo) {
    __nv_bfloat16 ha = __float2bfloat16(a), hb = __float2bfloat16(b);
    __nv_bfloat16 la = __float2bfloat16(a - __bfloat162float(ha));
    __nv_bfloat16 lb = __float2bfloat16(b - __bfloat162float(hb));
    __nv_bfloat162 H; H.x = ha; H.y = hb;
    __nv_bfloat162 L; L.x = la; L.y = lb;
    hi = *(uint32_t*)&H; lo = *(uint32_t*)&L;
}

#define LDSM_X4(d, addr)                                                        \
    asm volatile("ldmatrix.sync.aligned.m8n8.x4.shared.b16 {%0,%1,%2,%3}, [%4];"\
        : "=r"((d)[0]), "=r"((d)[1]), "=r"((d)[2]), "=r"((d)[3]) : "r"(addr))
#define MMA16816(c, a0, a1, a2, a3, b0, b1)                                     \
    asm volatile("mma.sync.aligned.m16n8k16.row.col.f32.bf16.bf16.f32 "         \
        "{%0,%1,%2,%3}, {%4,%5,%6,%7}, {%8,%9}, {%0,%1,%2,%3};"                 \
        : "+f"((c)[0]), "+f"((c)[1]), "+f"((c)[2]), "+f"((c)[3])                \
        : "r"(a0), "r"(a1), "r"(a2), "r"(a3), "r"(b0), "r"(b1))
#define MMA16816F16(c, a0, a1, a2, a3, b0, b1)                                  \
    asm volatile("mma.sync.aligned.m16n8k16.row.col.f32.f16.f16.f32 "           \
        "{%0,%1,%2,%3}, {%4,%5,%6,%7}, {%8,%9}, {%0,%1,%2,%3};"                 \
        : "+f"((c)[0]), "+f"((c)[1]), "+f"((c)[2]), "+f"((c)[3])                \
        : "r"(a0), "r"(a1), "r"(a2), "r"(a3), "r"(b0), "r"(b1))

// ---------------------------------------------------------------------------
// Split-bf16 HMMA GEMM (validated R14: 3-stage cp.async, 1 barrier/k-tile).
// ---------------------------------------------------------------------------
template <int EPI>
__global__ __launch_bounds__(256) void gemm3_kernel(
    const __nv_bfloat16* __restrict__ A, const __nv_bfloat16* __restrict__ B,
    const float* __restrict__ bias,
    float* __restrict__ C, int ldc,
    __nv_bfloat16* __restrict__ C3, int c3stride, int c3seg,
    int Ksz, int KT0)
{
    extern __shared__ char dynsm[];
    char* base = (char*)(((uintptr_t)dynsm + 127) & ~(uintptr_t)127);
    __shared__ float s_bias[128];

    const int tid  = threadIdx.x;
    const int wid  = tid >> 5;
    const int lane = tid & 31;
    const int bm = blockIdx.y * 128;
    const int bn = blockIdx.x * 128;
    const int K2 = 2 * Ksz;
    const int KT = 3 * KT0;

    if (EPI > 0 && tid < 128) s_bias[tid] = bias[bn + tid];

    uint32_t sA[3], sB[3];
#pragma unroll
    for (int s = 0; s < 3; s++) {
        sA[s] = smem_u32(base + s * 32768);
        sB[s] = sA[s] + 16384;
    }

    const __nv_bfloat16* Abase = A + (size_t)bm * K2;
    const __nv_bfloat16* Bbase = B + (size_t)bn * K2;

#define LOAD_STAGE(s, u)                                                        \
    do {                                                                        \
        const int _seg = ((u) >= 2 * KT0) ? 2 : (((u) >= KT0) ? 1 : 0);         \
        const int _kin = (u) - _seg * KT0;                                      \
        const __nv_bfloat16* Ag = Abase + (size_t)((_seg == 2) ? Ksz : 0)       \
                                        + (size_t)_kin * 64;                    \
        const __nv_bfloat16* Bg = Bbase + (size_t)((_seg == 1) ? Ksz : 0)       \
                                        + (size_t)_kin * 64;                    \
        _Pragma("unroll")                                                       \
        for (int i = 0; i < 4; i++) {                                           \
            int idx = tid + i * 256;                                            \
            int r = idx >> 3, ch = idx & 7;                                     \
            uint32_t off = (uint32_t)(r * 128 + ((ch ^ (r & 7)) << 4));         \
            asm volatile("cp.async.cg.shared.global [%0], [%1], 16;"            \
                :: "r"(sA[s] + off), "l"(Ag + (size_t)r * K2 + ch * 8)          \
                : "memory");                                                    \
            asm volatile("cp.async.cg.shared.global [%0], [%1], 16;"            \
                :: "r"(sB[s] + off), "l"(Bg + (size_t)r * K2 + ch * 8)          \
                : "memory");                                                    \
        }                                                                       \
        asm volatile("cp.async.commit_group;" ::: "memory");                    \
    } while (0)

    const int wm = (wid >> 2) * 64;
    const int wn = (wid & 3) * 32;
    const int a_roff = ((lane >> 3) & 1) * 8 + (lane & 7);
    const int a_koff = lane >> 4;
    const int b_roff = ((lane >> 4) & 1) * 8 + (lane & 7);
    const int b_koff = (lane >> 3) & 1;

    float acc[4][4][4];
#pragma unroll
    for (int mt = 0; mt < 4; mt++)
#pragma unroll
        for (int nt = 0; nt < 4; nt++)
#pragma unroll
            for (int e = 0; e < 4; e++) acc[mt][nt][e] = 0.f;

    LOAD_STAGE(0, 0);
    LOAD_STAGE(1, 1);

    int sidx = 0;
    for (int t = 0; t < KT; t++) {
        if (t + 1 < KT) {
            asm volatile("cp.async.wait_group 1;" ::: "memory");
        } else {
            asm volatile("cp.async.wait_group 0;" ::: "memory");
        }
        __syncthreads();
        if (t + 2 < KT) {
            const int ns = (sidx + 2 >= 3) ? sidx - 1 : sidx + 2;
            LOAD_STAGE(ns, t + 2);
        }

        const uint32_t cA = sA[sidx], cB = sB[sidx];
#pragma unroll
        for (int ks = 0; ks < 4; ks++) {
            uint32_t af[4][4], bf2[2][4];
#pragma unroll
            for (int mt = 0; mt < 4; mt++) {
                int rA = wm + mt * 16 + a_roff;
                uint32_t addr = cA + rA * 128 +
                                ((((ks << 1) + a_koff) ^ (rA & 7)) << 4);
                LDSM_X4(af[mt], addr);
            }
#pragma unroll
            for (int p = 0; p < 2; p++) {
                int rB = wn + p * 16 + b_roff;
                uint32_t addr = cB + rB * 128 +
                                ((((ks << 1) + b_koff) ^ (rB & 7)) << 4);
                LDSM_X4(bf2[p], addr);
            }
#pragma unroll
            for (int mt = 0; mt < 4; mt++)
#pragma unroll
                for (int nt = 0; nt < 4; nt++) {
                    uint32_t b0 = bf2[nt >> 1][(nt & 1) * 2];
                    uint32_t b1 = bf2[nt >> 1][(nt & 1) * 2 + 1];
                    MMA16816(acc[mt][nt], af[mt][0], af[mt][1], af[mt][2], af[mt][3], b0, b1);
                }
        }
        sidx = (sidx + 1 == 3) ? 0 : sidx + 1;
    }
#undef LOAD_STAGE

    const int lr = lane >> 2;
    const int lc = (lane & 3) * 2;
#pragma unroll
    for (int mt = 0; mt < 4; mt++) {
#pragma unroll
        for (int nt = 0; nt < 4; nt++) {
            float* c = acc[mt][nt];
            const int tc   = wn + nt * 8 + lc;
            const int row0 = bm + wm + mt * 16 + lr;
            if (EPI == 1) {
                float h0a = fmaxf(c[0] + s_bias[tc],     0.f);
                float h1a = fmaxf(c[1] + s_bias[tc + 1], 0.f);
                float h0b = fmaxf(c[2] + s_bias[tc],     0.f);
                float h1b = fmaxf(c[3] + s_bias[tc + 1], 0.f);
                const int nn = bn + tc;
#pragma unroll
                for (int half = 0; half < 2; half++) {
                    float v0 = half ? h0b : h0a;
                    float v1 = half ? h1b : h1a;
                    uint32_t hh, ll;
                    split2(v0, v1, hh, ll);
                    __nv_bfloat16* o = C3 + (size_t)(row0 + half * 8) * c3stride;
                    *(uint32_t*)(o + nn)         = hh;
                    *(uint32_t*)(o + c3seg + nn) = ll;
                }
            } else {
                float b0v = (EPI == 2) ? s_bias[tc]     : 0.f;
                float b1v = (EPI == 2) ? s_bias[tc + 1] : 0.f;
                float2 v0 = make_float2(c[0] + b0v, c[1] + b1v);
                float2 v1 = make_float2(c[2] + b0v, c[3] + b1v);
                *(float2*)(C + (size_t)row0 * ldc + bn + tc)       = v0;
                *(float2*)(C + (size_t)(row0 + 8) * ldc + bn + tc) = v1;
            }
        }
    }
}

// ---------------------------------------------------------------------------
// HMMA flash attention, dedup smem: Q/K rows = (hi|lo) 272B (hi stored ONCE);
// per-k-tile offset tables give segment patterns Q=(hi,hi,lo), K=(hi,lo,hi).
// f16x2 ex2 softmax, f16 PV, ones-column row sums.
// smem: Q phase 128x272 = 34816; loop: K 64x272 (17408) + Vt(f16) 64x144.
// ---------------------------------------------------------------------------
__global__ __launch_bounds__(256) void attn_mma_kernel(
    const float* __restrict__ Qg, const float* __restrict__ Kg,
    const float* __restrict__ Vg, float* __restrict__ Og)
{
    extern __shared__ char smraw[];
    char* smp = smraw;
    const uint32_t sQ = smem_u32(smraw);
    const uint32_t sK = sQ;
    const uint32_t sV = sQ + 17408;

    const int tid = threadIdx.x;
    const int wid = tid >> 5, lane = tid & 31;
    const int bh = blockIdx.y;
    const int b = bh >> 4, h = bh & 15;
    const int q0 = blockIdx.x * 128;
    const float* Qbase = Qg + (size_t)b * Tn * LDQKV + h * DKn;
    const float* Kbase = Kg + (size_t)b * Tn * LDQKV + h * DKn;
    const float* Vbase = Vg + (size_t)b * Tn * LDQKV + h * DKn;
    float* Obase = Og + (size_t)b * Tn * Dn + h * DKn;

    const int a_roff = ((lane >> 3) & 1) * 8 + (lane & 7);
    const int a_koff = lane >> 4;
    const int b_roff = ((lane >> 4) & 1) * 8 + (lane & 7);
    const int b_koff = (lane >> 3) & 1;

    // segment patterns: Q=(hi,hi,lo), K=(hi,lo,hi); hi at +0, lo at +128
    const int QOFF[12] = {0,32,64,96, 0,32,64,96, 128,160,192,224};
    const int KOFF[12] = {0,32,64,96, 128,160,192,224, 0,32,64,96};

    // ---- stage Q split (scaled by 1/8): (hi|lo), 272B rows
#pragma unroll
    for (int i = 0; i < 8; i++) {
        int idx = tid + i * 256;
        int r = idx >> 4, c4 = (idx & 15) * 4;
        float4 q = *(const float4*)(Qbase + (size_t)(q0 + r) * LDQKV + c4);
        q.x *= 0.125f; q.y *= 0.125f; q.z *= 0.125f; q.w *= 0.125f;
        uint32_t h0, l0, h1, l1;
        split2(q.x, q.y, h0, l0);
        split2(q.z, q.w, h1, l1);
        char* row = smp + r * 272;
        *(uint2*)(row + c4 * 2)       = make_uint2(h0, h1);
        *(uint2*)(row + 128 + c4 * 2) = make_uint2(l0, l1);
    }
    __syncthreads();

    uint32_t qf[12][4];
#pragma unroll
    for (int kt = 0; kt < 12; kt++) {
        uint32_t addr = sQ + (wid * 16 + a_roff) * 272 + QOFF[kt] + a_koff * 16;
        LDSM_X4(qf[kt], addr);
    }
    __syncthreads();

    float m0 = -1e30f, m1 = -1e30f;
    float of[8][4], osum[4];
#pragma unroll
    for (int j = 0; j < 8; j++)
#pragma unroll
        for (int e = 0; e < 4; e++) of[j][e] = 0.f;
#pragma unroll
    for (int e = 0; e < 4; e++) osum[e] = 0.f;

    const uint32_t ONES_H2 = 0x3C003C00u;   // f16 (1.0, 1.0)
    const float L2E = 1.4426950408889634f;

    for (int kv0 = 0; kv0 < Tn; kv0 += 64) {
        // ---- stage K split (hi|lo) + V transposed f16
#pragma unroll
        for (int i = 0; i < 4; i++) {
            int idx = tid + i * 256;
            int r = idx >> 4, c4 = (idx & 15) * 4;
            float4 k = *(const float4*)(Kbase + (size_t)(kv0 + r) * LDQKV + c4);
            uint32_t h0, lo0, h1, lo1;
            split2(k.x, k.y, h0, lo0);
            split2(k.z, k.w, h1, lo1);
            char* row = smp + r * 272;
            *(uint2*)(row + c4 * 2)       = make_uint2(h0, h1);
            *(uint2*)(row + 128 + c4 * 2) = make_uint2(lo0, lo1);

            float4 v = *(const float4*)(Vbase + (size_t)(kv0 + r) * LDQKV + c4);
            char* vb = smp + 17408 + r * 2;
            *(__half*)(vb + (c4 + 0) * 144) = __float2half(v.x);
            *(__half*)(vb + (c4 + 1) * 144) = __float2half(v.y);
            *(__half*)(vb + (c4 + 2) * 144) = __float2half(v.z);
            *(__half*)(vb + (c4 + 3) * 144) = __float2half(v.w);
        }
        __syncthreads();

        // ---- S = Q' . K'^T  (segment-mapped k-tiles)
        float sf[8][4];
#pragma unroll
        for (int nt = 0; nt < 8; nt++)
#pragma unroll
            for (int e = 0; e < 4; e++) sf[nt][e] = 0.f;

#pragma unroll
        for (int kt = 0; kt < 12; kt++) {
            uint32_t bf[4][4];
#pragma unroll
            for (int p = 0; p < 4; p++) {
                uint32_t addr = sK + (p * 16 + b_roff) * 272 + KOFF[kt] + b_koff * 16;
                LDSM_X4(bf[p], addr);
            }
#pragma unroll
            for (int nt = 0; nt < 8; nt++) {
                uint32_t bb0 = bf[nt >> 1][(nt & 1) * 2];
                uint32_t bb1 = bf[nt >> 1][(nt & 1) * 2 + 1];
                MMA16816(sf[nt], qf[kt][0], qf[kt][1], qf[kt][2], qf[kt][3], bb0, bb1);
            }
        }

        // ---- online max
        float mx0 = -1e30f, mx1 = -1e30f;
#pragma unroll
        for (int nt = 0; nt < 8; nt++) {
            mx0 = fmaxf(mx0, fmaxf(sf[nt][0], sf[nt][1]));
            mx1 = fmaxf(mx1, fmaxf(sf[nt][2], sf[nt][3]));
        }
        mx0 = fmaxf(mx0, __shfl_xor_sync(0xffffffffu, mx0, 1));
        mx0 = fmaxf(mx0, __shfl_xor_sync(0xffffffffu, mx0, 2));
        mx1 = fmaxf(mx1, __shfl_xor_sync(0xffffffffu, mx1, 1));
        mx1 = fmaxf(mx1, __shfl_xor_sync(0xffffffffu, mx1, 2));
        float mn0 = fmaxf(m0, mx0), mn1 = fmaxf(m1, mx1);
        float alpha0 = __expf(m0 - mn0), alpha1 = __expf(m1 - mn1);
        m0 = mn0; m1 = mn1;

        // ---- p = exp2((s - m) * log2e) in f16x2
        const float nb0 = mn0 * L2E, nb1 = mn1 * L2E;
        uint32_t hp[8][2];
#pragma unroll
        for (int nt = 0; nt < 8; nt++) {
            float t0 = fmaf(sf[nt][0], L2E, -nb0);
            float t1 = fmaf(sf[nt][1], L2E, -nb0);
            float t2 = fmaf(sf[nt][2], L2E, -nb1);
            float t3 = fmaf(sf[nt][3], L2E, -nb1);
            __half2 h01 = h2exp2(__floats2half2_rn(t0, t1));
            __half2 h23 = h2exp2(__floats2half2_rn(t2, t3));
            hp[nt][0] = *(uint32_t*)&h01;
            hp[nt][1] = *(uint32_t*)&h23;
        }

        // ---- rescale running outputs
#pragma unroll
        for (int j = 0; j < 8; j++) {
            of[j][0] *= alpha0; of[j][1] *= alpha0;
            of[j][2] *= alpha1; of[j][3] *= alpha1;
        }
        osum[0] *= alpha0; osum[1] *= alpha0;
        osum[2] *= alpha1; osum[3] *= alpha1;

        // ---- O += P @ V (f16) ; row-sum via ones column
#pragma unroll
        for (int g = 0; g < 4; g++) {
            uint32_t a0 = hp[2 * g][0];
            uint32_t a1 = hp[2 * g][1];
            uint32_t a2 = hp[2 * g + 1][0];
            uint32_t a3 = hp[2 * g + 1][1];
            uint32_t vf[4][4];
#pragma unroll
            for (int p = 0; p < 4; p++) {
                uint32_t addr = sV + (p * 16 + b_roff) * 144 + (g * 2 + b_koff) * 16;
                LDSM_X4(vf[p], addr);
            }
#pragma unroll
            for (int j = 0; j < 8; j++) {
                uint32_t bb0 = vf[j >> 1][(j & 1) * 2];
                uint32_t bb1 = vf[j >> 1][(j & 1) * 2 + 1];
                MMA16816F16(of[j], a0, a1, a2, a3, bb0, bb1);
            }
            MMA16816F16(osum, a0, a1, a2, a3, ONES_H2, ONES_H2);
        }
        __syncthreads();
    }

    // ---- write O (normalized)
    const float inv0 = 1.f / osum[0], inv1 = 1.f / osum[2];
    const int r0 = q0 + wid * 16 + (lane >> 2);
    const int cc = (lane & 3) * 2;
#pragma unroll
    for (int j = 0; j < 8; j++) {
        *(float2*)(Obase + (size_t)r0 * Dn + j * 8 + cc) =
            make_float2(of[j][0] * inv0, of[j][1] * inv0);
        *(float2*)(Obase + (size_t)(r0 + 8) * Dn + j * 8 + cc) =
            make_float2(of[j][2] * inv1, of[j][3] * inv1);
    }
}

// ---------------------------------------------------------------------------
// Weight transpose + split:  W[K,N] fp32  ->  B2[N, 2K] bf16 = (hi | lo)
// ---------------------------------------------------------------------------
__global__ __launch_bounds__(256) void wtrans2_kernel(
    const float* __restrict__ W, __nv_bfloat16* __restrict__ B2,
    int K, int N, int K2)
{
    __shared__ float t[32][33];
    const int n0 = blockIdx.x * 32, k0 = blockIdx.y * 32;
    const int tx = threadIdx.x & 31, ty = threadIdx.x >> 5;
#pragma unroll
    for (int i = 0; i < 4; i++)
        t[ty + 8 * i][tx] = W[(size_t)(k0 + ty + 8 * i) * N + n0 + tx];
    __syncthreads();
#pragma unroll
    for (int i = 0; i < 4; i++) {
        int n = n0 + ty + 8 * i;
        int k = k0 + tx;
        float v = t[tx][ty + 8 * i];
        __nv_bfloat16 hi = __float2bfloat16(v);
        __nv_bfloat16 lo = __float2bfloat16(v - __bfloat162float(hi));
        __nv_bfloat16* row = B2 + (size_t)n * K2;
        row[k] = hi; row[K + k] = lo;
    }
}

// x fp32 [4096,1024] -> A2 bf16 [4096, 2048] = (hi | lo)
__global__ __launch_bounds__(256) void conv2_kernel(
    const float* __restrict__ X, __nv_bfloat16* __restrict__ A2)
{
    const int m = blockIdx.x;
    const float* xr = X + (size_t)m * Dn;
    __nv_bfloat16* ar = A2 + (size_t)m * 2048;
#pragma unroll
    for (int i = 0; i < 4; i++) {
        int k = threadIdx.x + i * 256;
        float v = xr[k];
        __nv_bfloat16 hi = __float2bfloat16(v);
        __nv_bfloat16 lo = __float2bfloat16(v - __bfloat162float(hi));
        ar[k] = hi; ar[Dn + k] = lo;
    }
}

// ---------------------------------------------------------------------------
// LayerNorm(a+b)*g+beta.  PAIR=1 also writes the (hi|lo) bf16 split.
// ---------------------------------------------------------------------------
template <int PAIR>
__global__ __launch_bounds__(256) void add_ln_kernel(
    const float* __restrict__ A, const float* __restrict__ Bv,
    const float* __restrict__ g, const float* __restrict__ beta,
    float* __restrict__ out, __nv_bfloat16* __restrict__ A2)
{
    const int row = blockIdx.x;
    const int tid = threadIdx.x;
    const float* a = A + (size_t)row * Dn;
    const float* b = Bv + (size_t)row * Dn;

    float v[4];
    float s = 0.f, s2 = 0.f;
#pragma unroll
    for (int i = 0; i < 4; i++) {
        int c = tid + i * 256;
        v[i] = a[c] + b[c];
        s += v[i];
        s2 += v[i] * v[i];
    }
#pragma unroll
    for (int off = 16; off >= 1; off >>= 1) {
        s  += __shfl_xor_sync(0xffffffffu, s,  off);
        s2 += __shfl_xor_sync(0xffffffffu, s2, off);
    }
    __shared__ float red[16];
    const int w = tid >> 5;
    if ((tid & 31) == 0) { red[w] = s; red[w + 8] = s2; }
    __syncthreads();
    float ts = 0.f, ts2 = 0.f;
#pragma unroll
    for (int i = 0; i < 8; i++) { ts += red[i]; ts2 += red[8 + i]; }
    const float mu  = ts * (1.f / Dn);
    const float var = ts2 * (1.f / Dn) - mu * mu;
    const float r = rsqrtf(var + 1e-5f);
    float* orow = out + (size_t)row * Dn;
    __nv_bfloat16* a2 = PAIR ? (A2 + (size_t)row * 2048) : nullptr;
#pragma unroll
    for (int i = 0; i < 4; i++) {
        int c = tid + i * 256;
        float y = (v[i] - mu) * r * g[c] + beta[c];
        orow[c] = y;
        if (PAIR) {
            __nv_bfloat16 hi = __float2bfloat16(y);
            __nv_bfloat16 lo = __float2bfloat16(y - __bfloat162float(hi));
            a2[c] = hi; a2[Dn + c] = lo;
        }
    }
}

// ---------------------------------------------------------------------------
extern "C" void kernel_launch(void* const* d_in, const int* in_sizes, int n_in,
                              void* d_out, int out_size)
{
    (void)in_sizes; (void)n_in; (void)out_size;
    const float* x    = (const float*)d_in[0];
    const float* Wq   = (const float*)d_in[1];
    const float* Wk   = (const float*)d_in[2];
    const float* Wv   = (const float*)d_in[3];
    const float* W1   = (const float*)d_in[4];
    const float* b1   = (const float*)d_in[5];
    const float* W2   = (const float*)d_in[6];
    const float* b2   = (const float*)d_in[7];
    const float* ln1g = (const float*)d_in[8];
    const float* ln1b = (const float*)d_in[9];
    const float* ln2g = (const float*)d_in[10];
    const float* ln2b = (const float*)d_in[11];
    float* out = (float*)d_out;

    __nv_bfloat16 *A2x, *B2qkv, *A2x1, *B2w1, *A2h, *B2w2;
    float *QKV, *att, *x1, *ff;
    cudaGetSymbolAddress((void**)&A2x,   g_A2x);
    cudaGetSymbolAddress((void**)&B2qkv, g_B2qkv);
    cudaGetSymbolAddress((void**)&QKV,   g_QKV);
    cudaGetSymbolAddress((void**)&att,   g_att);
    cudaGetSymbolAddress((void**)&x1,    g_x1);
    cudaGetSymbolAddress((void**)&A2x1,  g_A2x1);
    cudaGetSymbolAddress((void**)&B2w1,  g_B2w1);
    cudaGetSymbolAddress((void**)&A2h,   g_A2h);
    cudaGetSymbolAddress((void**)&B2w2,  g_B2w2);
    cudaGetSymbolAddress((void**)&ff,    g_ff);

    // side stream + events, created once on the (uncaptured) correctness call
    static cudaStream_t s_side = nullptr;
    static cudaEvent_t  ev_fork = nullptr, ev_join = nullptr;
    if (s_side == nullptr) {
        cudaStreamCreateWithFlags(&s_side, cudaStreamNonBlocking);
        cudaEventCreateWithFlags(&ev_fork, cudaEventDisableTiming);
        cudaEventCreateWithFlags(&ev_join, cudaEventDisableTiming);
    }

    const int GEMM_SMEM = 3 * 32768 + 128;
    const int ATT_SMEM  = 34816;
    cudaFuncSetAttribute(gemm3_kernel<0>, cudaFuncAttributeMaxDynamicSharedMemorySize, GEMM_SMEM);
    cudaFuncSetAttribute(gemm3_kernel<1>, cudaFuncAttributeMaxDynamicSharedMemorySize, GEMM_SMEM);
    cudaFuncSetAttribute(gemm3_kernel<2>, cudaFuncAttributeMaxDynamicSharedMemorySize, GEMM_SMEM);
    cudaFuncSetAttribute(attn_mma_kernel, cudaFuncAttributeMaxDynamicSharedMemorySize, ATT_SMEM);

    // ---- fork: W1/W2 transposes overlap QKV GEMM + attention ----
    cudaEventRecord(ev_fork, 0);
    cudaStreamWaitEvent(s_side, ev_fork, 0);
    wtrans2_kernel<<<dim3(DFn / 32, Dn / 32), 256, 0, s_side>>>(W1, B2w1, Dn,  DFn, 2048);
    wtrans2_kernel<<<dim3(Dn / 32, DFn / 32), 256, 0, s_side>>>(W2, B2w2, DFn, Dn,  8192);
    cudaEventRecord(ev_join, s_side);

    // ---- main: prep feeding QKV ----
    conv2_kernel<<<Mrows, 256>>>(x, A2x);
    wtrans2_kernel<<<dim3(Dn / 32, Dn / 32), 256>>>(Wq, B2qkv,                       Dn, Dn, 2048);
    wtrans2_kernel<<<dim3(Dn / 32, Dn / 32), 256>>>(Wk, B2qkv + (size_t)1024 * 2048, Dn, Dn, 2048);
    wtrans2_kernel<<<dim3(Dn / 32, Dn / 32), 256>>>(Wv, B2qkv + (size_t)2048 * 2048, Dn, Dn, 2048);

    // ---- QKV = x @ [Wq|Wk|Wv]  (M=4096, N=3072, K=1024) ----
    gemm3_kernel<0><<<dim3(3072 / 128, Mrows / 128), 256, GEMM_SMEM>>>(
        A2x, B2qkv, nullptr, QKV, 3072, nullptr, 0, 0, Dn, Dn / 64);

    // ---- attention (HMMA, f16 softmax/PV, dedup smem) ----
    attn_mma_kernel<<<dim3(Tn / 128, Bsz * Hn), 256, ATT_SMEM>>>(
        QKV, QKV + 1024, QKV + 2048, att);

    // ---- x1 = LN(x + att)  (+ (hi|lo) split for FFN1) ----
    add_ln_kernel<1><<<Mrows, 256>>>(x, att, ln1g, ln1b, x1, A2x1);

    // ---- join side stream before FFN1 ----
    cudaStreamWaitEvent(0, ev_join, 0);

    // ---- h1 = relu(x1 @ W1 + b1) -> bf16 (hi|lo)  (K=1024) ----
    gemm3_kernel<1><<<dim3(DFn / 128, Mrows / 128), 256, GEMM_SMEM>>>(
        A2x1, B2w1, b1, nullptr, 0, A2h, 8192, DFn, Dn, Dn / 64);

    // ---- ff = h1 @ W2 + b2  (K=4096) ----
    gemm3_kernel<2><<<dim3(Dn / 128, Mrows / 128), 256, GEMM_SMEM>>>(
        A2h, B2w2, b2, ff, Dn, nullptr, 0, 0, DFn, DFn / 64);

    // ---- out = LN(x1 + ff) ----
    add_ln_kernel<0><<<Mrows, 256>>>(x1, ff, ln2g, ln2b, out, nullptr);
}

// round 16
// speedup vs baseline: 1.1449x; 1.0191x over previous
#include <cuda_runtime.h>
#include <cuda_bf16.h>
#include <cuda_fp16.h>
#include <cstdint>
#include <cstddef>

// ---------------------------------------------------------------------------
// EncoderStack B=4 T=1024 D=1024 H=16 DK=64 DF=4096, fp32 in/out.
// GEMMs + attention via mma.sync bf16 split-precision (K'=3K, segment-mapped
// (hi|lo) storage).  Attention: f16x2 ex2 softmax, f16 PV, ones-column sums,
// dedup smem + register-prefetched K/V loads.  Merged QKV weight transpose;
// W1/W2 transposes overlap main chain on a side stream.
// ---------------------------------------------------------------------------
#define Bsz 4
#define Tn  1024
#define Dn  1024
#define Hn  16
#define DKn 64
#define DFn 4096
#define Mrows 4096
#define LDQKV 3072

// ---- scratch (device globals; allocation-free per harness rules) ----------
__device__ __nv_bfloat16 g_A2x [Mrows * 2048];     // x  (hi|lo)
__device__ __nv_bfloat16 g_B2qkv[3072 * 2048];     // Wq|Wk|Wv^T (hi|lo)
__device__ float         g_QKV [Mrows * 3072];
__device__ float         g_att [Mrows * Dn];
__device__ float         g_x1  [Mrows * Dn];
__device__ __nv_bfloat16 g_A2x1[Mrows * 2048];     // x1 (hi|lo)
__device__ __nv_bfloat16 g_B2w1[DFn * 2048];       // W1^T (hi|lo)
__device__ __nv_bfloat16 g_A2h [Mrows * 8192];     // relu(h1) (hi|lo)
__device__ __nv_bfloat16 g_B2w2[Dn * 8192];        // W2^T (hi|lo)
__device__ float         g_ff  [Mrows * Dn];

__device__ __forceinline__ uint32_t smem_u32(const void* p) {
    uint32_t a;
    asm("{ .reg .u64 t; cvta.to.shared.u64 t, %1; cvt.u32.u64 %0, t; }"
        : "=r"(a) : "l"(p));
    return a;
}
__device__ __forceinline__ void split2(float a, float b, uint32_t& hi, uint32_t& lo) {
    __nv_bfloat16 ha = __float2bfloat16(a), hb = __float2bfloat16(b);
    __nv_bfloat16 la = __float2bfloat16(a - __bfloat162float(ha));
    __nv_bfloat16 lb = __float2bfloat16(b - __bfloat162float(hb));
    __nv_bfloat162 H; H.x = ha; H.y = hb;
    __nv_bfloat162 L; L.x = la; L.y = lb;
    hi = *(uint32_t*)&H; lo = *(uint32_t*)&L;
}

#define LDSM_X4(d, addr)                                                        \
    asm volatile("ldmatrix.sync.aligned.m8n8.x4.shared.b16 {%0,%1,%2,%3}, [%4];"\
        : "=r"((d)[0]), "=r"((d)[1]), "=r"((d)[2]), "=r"((d)[3]) : "r"(addr))
#define MMA16816(c, a0, a1, a2, a3, b0, b1)                                     \
    asm volatile("mma.sync.aligned.m16n8k16.row.col.f32.bf16.bf16.f32 "         \
        "{%0,%1,%2,%3}, {%4,%5,%6,%7}, {%8,%9}, {%0,%1,%2,%3};"                 \
        : "+f"((c)[0]), "+f"((c)[1]), "+f"((c)[2]), "+f"((c)[3])                \
        : "r"(a0), "r"(a1), "r"(a2), "r"(a3), "r"(b0), "r"(b1))
#define MMA16816F16(c, a0, a1, a2, a3, b0, b1)                                  \
    asm volatile("mma.sync.aligned.m16n8k16.row.col.f32.f16.f16.f32 "           \
        "{%0,%1,%2,%3}, {%4,%5,%6,%7}, {%8,%9}, {%0,%1,%2,%3};"                 \
        : "+f"((c)[0]), "+f"((c)[1]), "+f"((c)[2]), "+f"((c)[3])                \
        : "r"(a0), "r"(a1), "r"(a2), "r"(a3), "r"(b0), "r"(b1))

// ---------------------------------------------------------------------------
// Split-bf16 HMMA GEMM (validated: 3-stage cp.async, 1 barrier/k-tile).
// ---------------------------------------------------------------------------
template <int EPI>
__global__ __launch_bounds__(256) void gemm3_kernel(
    const __nv_bfloat16* __restrict__ A, const __nv_bfloat16* __restrict__ B,
    const float* __restrict__ bias,
    float* __restrict__ C, int ldc,
    __nv_bfloat16* __restrict__ C3, int c3stride, int c3seg,
    int Ksz, int KT0)
{
    extern __shared__ char dynsm[];
    char* base = (char*)(((uintptr_t)dynsm + 127) & ~(uintptr_t)127);
    __shared__ float s_bias[128];

    const int tid  = threadIdx.x;
    const int wid  = tid >> 5;
    const int lane = tid & 31;
    const int bm = blockIdx.y * 128;
    const int bn = blockIdx.x * 128;
    const int K2 = 2 * Ksz;
    const int KT = 3 * KT0;

    if (EPI > 0 && tid < 128) s_bias[tid] = bias[bn + tid];

    uint32_t sA[3], sB[3];
#pragma unroll
    for (int s = 0; s < 3; s++) {
        sA[s] = smem_u32(base + s * 32768);
        sB[s] = sA[s] + 16384;
    }

    const __nv_bfloat16* Abase = A + (size_t)bm * K2;
    const __nv_bfloat16* Bbase = B + (size_t)bn * K2;

#define LOAD_STAGE(s, u)                                                        \
    do {                                                                        \
        const int _seg = ((u) >= 2 * KT0) ? 2 : (((u) >= KT0) ? 1 : 0);         \
        const int _kin = (u) - _seg * KT0;                                      \
        const __nv_bfloat16* Ag = Abase + (size_t)((_seg == 2) ? Ksz : 0)       \
                                        + (size_t)_kin * 64;                    \
        const __nv_bfloat16* Bg = Bbase + (size_t)((_seg == 1) ? Ksz : 0)       \
                                        + (size_t)_kin * 64;                    \
        _Pragma("unroll")                                                       \
        for (int i = 0; i < 4; i++) {                                           \
            int idx = tid + i * 256;                                            \
            int r = idx >> 3, ch = idx & 7;                                     \
            uint32_t off = (uint32_t)(r * 128 + ((ch ^ (r & 7)) << 4));         \
            asm volatile("cp.async.cg.shared.global [%0], [%1], 16;"            \
                :: "r"(sA[s] + off), "l"(Ag + (size_t)r * K2 + ch * 8)          \
                : "memory");                                                    \
            asm volatile("cp.async.cg.shared.global [%0], [%1], 16;"            \
                :: "r"(sB[s] + off), "l"(Bg + (size_t)r * K2 + ch * 8)          \
                : "memory");                                                    \
        }                                                                       \
        asm volatile("cp.async.commit_group;" ::: "memory");                    \
    } while (0)

    const int wm = (wid >> 2) * 64;
    const int wn = (wid & 3) * 32;
    const int a_roff = ((lane >> 3) & 1) * 8 + (lane & 7);
    const int a_koff = lane >> 4;
    const int b_roff = ((lane >> 4) & 1) * 8 + (lane & 7);
    const int b_koff = (lane >> 3) & 1;

    float acc[4][4][4];
#pragma unroll
    for (int mt = 0; mt < 4; mt++)
#pragma unroll
        for (int nt = 0; nt < 4; nt++)
#pragma unroll
            for (int e = 0; e < 4; e++) acc[mt][nt][e] = 0.f;

    LOAD_STAGE(0, 0);
    LOAD_STAGE(1, 1);

    int sidx = 0;
    for (int t = 0; t < KT; t++) {
        if (t + 1 < KT) {
            asm volatile("cp.async.wait_group 1;" ::: "memory");
        } else {
            asm volatile("cp.async.wait_group 0;" ::: "memory");
        }
        __syncthreads();
        if (t + 2 < KT) {
            const int ns = (sidx + 2 >= 3) ? sidx - 1 : sidx + 2;
            LOAD_STAGE(ns, t + 2);
        }

        const uint32_t cA = sA[sidx], cB = sB[sidx];
#pragma unroll
        for (int ks = 0; ks < 4; ks++) {
            uint32_t af[4][4], bf2[2][4];
#pragma unroll
            for (int mt = 0; mt < 4; mt++) {
                int rA = wm + mt * 16 + a_roff;
                uint32_t addr = cA + rA * 128 +
                                ((((ks << 1) + a_koff) ^ (rA & 7)) << 4);
                LDSM_X4(af[mt], addr);
            }
#pragma unroll
            for (int p = 0; p < 2; p++) {
                int rB = wn + p * 16 + b_roff;
                uint32_t addr = cB + rB * 128 +
                                ((((ks << 1) + b_koff) ^ (rB & 7)) << 4);
                LDSM_X4(bf2[p], addr);
            }
#pragma unroll
            for (int mt = 0; mt < 4; mt++)
#pragma unroll
                for (int nt = 0; nt < 4; nt++) {
                    uint32_t b0 = bf2[nt >> 1][(nt & 1) * 2];
                    uint32_t b1 = bf2[nt >> 1][(nt & 1) * 2 + 1];
                    MMA16816(acc[mt][nt], af[mt][0], af[mt][1], af[mt][2], af[mt][3], b0, b1);
                }
        }
        sidx = (sidx + 1 == 3) ? 0 : sidx + 1;
    }
#undef LOAD_STAGE

    const int lr = lane >> 2;
    const int lc = (lane & 3) * 2;
#pragma unroll
    for (int mt = 0; mt < 4; mt++) {
#pragma unroll
        for (int nt = 0; nt < 4; nt++) {
            float* c = acc[mt][nt];
            const int tc   = wn + nt * 8 + lc;
            const int row0 = bm + wm + mt * 16 + lr;
            if (EPI == 1) {
                float h0a = fmaxf(c[0] + s_bias[tc],     0.f);
                float h1a = fmaxf(c[1] + s_bias[tc + 1], 0.f);
                float h0b = fmaxf(c[2] + s_bias[tc],     0.f);
                float h1b = fmaxf(c[3] + s_bias[tc + 1], 0.f);
                const int nn = bn + tc;
#pragma unroll
                for (int half = 0; half < 2; half++) {
                    float v0 = half ? h0b : h0a;
                    float v1 = half ? h1b : h1a;
                    uint32_t hh, ll;
                    split2(v0, v1, hh, ll);
                    __nv_bfloat16* o = C3 + (size_t)(row0 + half * 8) * c3stride;
                    *(uint32_t*)(o + nn)         = hh;
                    *(uint32_t*)(o + c3seg + nn) = ll;
                }
            } else {
                float b0v = (EPI == 2) ? s_bias[tc]     : 0.f;
                float b1v = (EPI == 2) ? s_bias[tc + 1] : 0.f;
                float2 v0 = make_float2(c[0] + b0v, c[1] + b1v);
                float2 v1 = make_float2(c[2] + b0v, c[3] + b1v);
                *(float2*)(C + (size_t)row0 * ldc + bn + tc)       = v0;
                *(float2*)(C + (size_t)(row0 + 8) * ldc + bn + tc) = v1;
            }
        }
    }
}

// ---------------------------------------------------------------------------
// HMMA flash attention, dedup smem + register-prefetched K/V global loads.
// Q/K rows (hi|lo) 272B; seg patterns Q=(hi,hi,lo), K=(hi,lo,hi) via tables.
// f16x2 ex2 softmax, f16 PV, ones-column row sums.
// smem: Q phase 128x272 = 34816; loop: K 64x272 (17408) + Vt(f16) 64x144.
// ---------------------------------------------------------------------------
__global__ __launch_bounds__(256) void attn_mma_kernel(
    const float* __restrict__ Qg, const float* __restrict__ Kg,
    const float* __restrict__ Vg, float* __restrict__ Og)
{
    extern __shared__ char smraw[];
    char* smp = smraw;
    const uint32_t sQ = smem_u32(smraw);
    const uint32_t sK = sQ;
    const uint32_t sV = sQ + 17408;

    const int tid = threadIdx.x;
    const int wid = tid >> 5, lane = tid & 31;
    const int bh = blockIdx.y;
    const int b = bh >> 4, h = bh & 15;
    const int q0 = blockIdx.x * 128;
    const float* Qbase = Qg + (size_t)b * Tn * LDQKV + h * DKn;
    const float* Kbase = Kg + (size_t)b * Tn * LDQKV + h * DKn;
    const float* Vbase = Vg + (size_t)b * Tn * LDQKV + h * DKn;
    float* Obase = Og + (size_t)b * Tn * Dn + h * DKn;

    const int a_roff = ((lane >> 3) & 1) * 8 + (lane & 7);
    const int a_koff = lane >> 4;
    const int b_roff = ((lane >> 4) & 1) * 8 + (lane & 7);
    const int b_koff = (lane >> 3) & 1;

    const int QOFF[12] = {0,32,64,96, 0,32,64,96, 128,160,192,224};
    const int KOFF[12] = {0,32,64,96, 128,160,192,224, 0,32,64,96};

    // ---- stage Q split (scaled by 1/8): (hi|lo), 272B rows
#pragma unroll
    for (int i = 0; i < 8; i++) {
        int idx = tid + i * 256;
        int r = idx >> 4, c4 = (idx & 15) * 4;
        float4 q = *(const float4*)(Qbase + (size_t)(q0 + r) * LDQKV + c4);
        q.x *= 0.125f; q.y *= 0.125f; q.z *= 0.125f; q.w *= 0.125f;
        uint32_t h0, l0, h1, l1;
        split2(q.x, q.y, h0, l0);
        split2(q.z, q.w, h1, l1);
        char* row = smp + r * 272;
        *(uint2*)(row + c4 * 2)       = make_uint2(h0, h1);
        *(uint2*)(row + 128 + c4 * 2) = make_uint2(l0, l1);
    }
    __syncthreads();

    uint32_t qf[12][4];
#pragma unroll
    for (int kt = 0; kt < 12; kt++) {
        uint32_t addr = sQ + (wid * 16 + a_roff) * 272 + QOFF[kt] + a_koff * 16;
        LDSM_X4(qf[kt], addr);
    }
    __syncthreads();

    float m0 = -1e30f, m1 = -1e30f;
    float of[8][4], osum[4];
#pragma unroll
    for (int j = 0; j < 8; j++)
#pragma unroll
        for (int e = 0; e < 4; e++) of[j][e] = 0.f;
#pragma unroll
    for (int e = 0; e < 4; e++) osum[e] = 0.f;

    const uint32_t ONES_H2 = 0x3C003C00u;
    const float L2E = 1.4426950408889634f;

    // per-thread staging coordinates (fixed across iterations)
    const int pr = tid >> 4;            // row 0..15 base (+16i)
    const int pc4 = (tid & 15) * 4;     // col 0..60

    // ---- register prefetch buffers + prologue load (kv0 = 0)
    float4 kreg[4], vreg[4];
#pragma unroll
    for (int i = 0; i < 4; i++) {
        int r = pr + i * 16;
        kreg[i] = *(const float4*)(Kbase + (size_t)r * LDQKV + pc4);
        vreg[i] = *(const float4*)(Vbase + (size_t)r * LDQKV + pc4);
    }

    for (int kv0 = 0; kv0 < Tn; kv0 += 64) {
        // ---- store prefetched K split (hi|lo) + V transposed f16
#pragma unroll
        for (int i = 0; i < 4; i++) {
            int r = pr + i * 16;
            uint32_t h0, lo0, h1, lo1;
            split2(kreg[i].x, kreg[i].y, h0, lo0);
            split2(kreg[i].z, kreg[i].w, h1, lo1);
            char* row = smp + r * 272;
            *(uint2*)(row + pc4 * 2)       = make_uint2(h0, h1);
            *(uint2*)(row + 128 + pc4 * 2) = make_uint2(lo0, lo1);

            char* vb = smp + 17408 + r * 2;
            *(__half*)(vb + (pc4 + 0) * 144) = __float2half(vreg[i].x);
            *(__half*)(vb + (pc4 + 1) * 144) = __float2half(vreg[i].y);
            *(__half*)(vb + (pc4 + 2) * 144) = __float2half(vreg[i].z);
            *(__half*)(vb + (pc4 + 3) * 144) = __float2half(vreg[i].w);
        }
        __syncthreads();

        // ---- issue next tile's global loads (hidden under mma below)
        if (kv0 + 64 < Tn) {
            const int nkv = kv0 + 64;
#pragma unroll
            for (int i = 0; i < 4; i++) {
                int r = nkv + pr + i * 16;
                kreg[i] = *(const float4*)(Kbase + (size_t)r * LDQKV + pc4);
                vreg[i] = *(const float4*)(Vbase + (size_t)r * LDQKV + pc4);
            }
        }

        // ---- S = Q' . K'^T  (segment-mapped k-tiles)
        float sf[8][4];
#pragma unroll
        for (int nt = 0; nt < 8; nt++)
#pragma unroll
            for (int e = 0; e < 4; e++) sf[nt][e] = 0.f;

#pragma unroll
        for (int kt = 0; kt < 12; kt++) {
            uint32_t bf[4][4];
#pragma unroll
            for (int p = 0; p < 4; p++) {
                uint32_t addr = sK + (p * 16 + b_roff) * 272 + KOFF[kt] + b_koff * 16;
                LDSM_X4(bf[p], addr);
            }
#pragma unroll
            for (int nt = 0; nt < 8; nt++) {
                uint32_t bb0 = bf[nt >> 1][(nt & 1) * 2];
                uint32_t bb1 = bf[nt >> 1][(nt & 1) * 2 + 1];
                MMA16816(sf[nt], qf[kt][0], qf[kt][1], qf[kt][2], qf[kt][3], bb0, bb1);
            }
        }

        // ---- online max
        float mx0 = -1e30f, mx1 = -1e30f;
#pragma unroll
        for (int nt = 0; nt < 8; nt++) {
            mx0 = fmaxf(mx0, fmaxf(sf[nt][0], sf[nt][1]));
            mx1 = fmaxf(mx1, fmaxf(sf[nt][2], sf[nt][3]));
        }
        mx0 = fmaxf(mx0, __shfl_xor_sync(0xffffffffu, mx0, 1));
        mx0 = fmaxf(mx0, __shfl_xor_sync(0xffffffffu, mx0, 2));
        mx1 = fmaxf(mx1, __shfl_xor_sync(0xffffffffu, mx1, 1));
        mx1 = fmaxf(mx1, __shfl_xor_sync(0xffffffffu, mx1, 2));
        float mn0 = fmaxf(m0, mx0), mn1 = fmaxf(m1, mx1);
        float alpha0 = __expf(m0 - mn0), alpha1 = __expf(m1 - mn1);
        m0 = mn0; m1 = mn1;

        // ---- p = exp2((s - m) * log2e) in f16x2
        const float nb0 = mn0 * L2E, nb1 = mn1 * L2E;
        uint32_t hp[8][2];
#pragma unroll
        for (int nt = 0; nt < 8; nt++) {
            float t0 = fmaf(sf[nt][0], L2E, -nb0);
            float t1 = fmaf(sf[nt][1], L2E, -nb0);
            float t2 = fmaf(sf[nt][2], L2E, -nb1);
            float t3 = fmaf(sf[nt][3], L2E, -nb1);
            __half2 h01 = h2exp2(__floats2half2_rn(t0, t1));
            __half2 h23 = h2exp2(__floats2half2_rn(t2, t3));
            hp[nt][0] = *(uint32_t*)&h01;
            hp[nt][1] = *(uint32_t*)&h23;
        }

        // ---- rescale running outputs
#pragma unroll
        for (int j = 0; j < 8; j++) {
            of[j][0] *= alpha0; of[j][1] *= alpha0;
            of[j][2] *= alpha1; of[j][3] *= alpha1;
        }
        osum[0] *= alpha0; osum[1] *= alpha0;
        osum[2] *= alpha1; osum[3] *= alpha1;

        // ---- O += P @ V (f16) ; row-sum via ones column
#pragma unroll
        for (int g = 0; g < 4; g++) {
            uint32_t a0 = hp[2 * g][0];
            uint32_t a1 = hp[2 * g][1];
            uint32_t a2 = hp[2 * g + 1][0];
            uint32_t a3 = hp[2 * g + 1][1];
            uint32_t vf[4][4];
#pragma unroll
            for (int p = 0; p < 4; p++) {
                uint32_t addr = sV + (p * 16 + b_roff) * 144 + (g * 2 + b_koff) * 16;
                LDSM_X4(vf[p], addr);
            }
#pragma unroll
            for (int j = 0; j < 8; j++) {
                uint32_t bb0 = vf[j >> 1][(j & 1) * 2];
                uint32_t bb1 = vf[j >> 1][(j & 1) * 2 + 1];
                MMA16816F16(of[j], a0, a1, a2, a3, bb0, bb1);
            }
            MMA16816F16(osum, a0, a1, a2, a3, ONES_H2, ONES_H2);
        }
        __syncthreads();
    }

    // ---- write O (normalized)
    const float inv0 = 1.f / osum[0], inv1 = 1.f / osum[2];
    const int r0 = q0 + wid * 16 + (lane >> 2);
    const int cc = (lane & 3) * 2;
#pragma unroll
    for (int j = 0; j < 8; j++) {
        *(float2*)(Obase + (size_t)r0 * Dn + j * 8 + cc) =
            make_float2(of[j][0] * inv0, of[j][1] * inv0);
        *(float2*)(Obase + (size_t)(r0 + 8) * Dn + j * 8 + cc) =
            make_float2(of[j][2] * inv1, of[j][3] * inv1);
    }
}

// ---------------------------------------------------------------------------
// Weight transpose + split:  W[K,N] fp32  ->  B2[N, 2K] bf16 = (hi | lo)
// ---------------------------------------------------------------------------
__global__ __launch_bounds__(256) void wtrans2_kernel(
    const float* __restrict__ W, __nv_bfloat16* __restrict__ B2,
    int K, int N, int K2)
{
    __shared__ float t[32][33];
    const int n0 = blockIdx.x * 32, k0 = blockIdx.y * 32;
    const int tx = threadIdx.x & 31, ty = threadIdx.x >> 5;
#pragma unroll
    for (int i = 0; i < 4; i++)
        t[ty + 8 * i][tx] = W[(size_t)(k0 + ty + 8 * i) * N + n0 + tx];
    __syncthreads();
#pragma unroll
    for (int i = 0; i < 4; i++) {
        int n = n0 + ty + 8 * i;
        int k = k0 + tx;
        float v = t[tx][ty + 8 * i];
        __nv_bfloat16 hi = __float2bfloat16(v);
        __nv_bfloat16 lo = __float2bfloat16(v - __bfloat162float(hi));
        __nv_bfloat16* row = B2 + (size_t)n * K2;
        row[k] = hi; row[K + k] = lo;
    }
}

// Merged Wq/Wk/Wv transpose (grid.z selects matrix) -> B2qkv rows z*1024..
__global__ __launch_bounds__(256) void wtrans2_qkv_kernel(
    const float* __restrict__ Wq, const float* __restrict__ Wk,
    const float* __restrict__ Wv, __nv_bfloat16* __restrict__ B2)
{
    const float* W = (blockIdx.z == 0) ? Wq : (blockIdx.z == 1) ? Wk : Wv;
    __nv_bfloat16* B2z = B2 + (size_t)blockIdx.z * 1024 * 2048;
    __shared__ float t[32][33];
    const int n0 = blockIdx.x * 32, k0 = blockIdx.y * 32;
    const int tx = threadIdx.x & 31, ty = threadIdx.x >> 5;
#pragma unroll
    for (int i = 0; i < 4; i++)
        t[ty + 8 * i][tx] = W[(size_t)(k0 + ty + 8 * i) * 1024 + n0 + tx];
    __syncthreads();
#pragma unroll
    for (int i = 0; i < 4; i++) {
        int n = n0 + ty + 8 * i;
        int k = k0 + tx;
        float v = t[tx][ty + 8 * i];
        __nv_bfloat16 hi = __float2bfloat16(v);
        __nv_bfloat16 lo = __float2bfloat16(v - __bfloat162float(hi));
        __nv_bfloat16* row = B2z + (size_t)n * 2048;
        row[k] = hi; row[1024 + k] = lo;
    }
}

// x fp32 [4096,1024] -> A2 bf16 [4096, 2048] = (hi | lo)
__global__ __launch_bounds__(256) void conv2_kernel(
    const float* __restrict__ X, __nv_bfloat16* __restrict__ A2)
{
    const int m = blockIdx.x;
    const float* xr = X + (size_t)m * Dn;
    __nv_bfloat16* ar = A2 + (size_t)m * 2048;
#pragma unroll
    for (int i = 0; i < 4; i++) {
        int k = threadIdx.x + i * 256;
        float v = xr[k];
        __nv_bfloat16 hi = __float2bfloat16(v);
        __nv_bfloat16 lo = __float2bfloat16(v - __bfloat162float(hi));
        ar[k] = hi; ar[Dn + k] = lo;
    }
}

// ---------------------------------------------------------------------------
// LayerNorm(a+b)*g+beta.  PAIR=1 also writes the (hi|lo) bf16 split.
// ---------------------------------------------------------------------------
template <int PAIR>
__global__ __launch_bounds__(256) void add_ln_kernel(
    const float* __restrict__ A, const float* __restrict__ Bv,
    const float* __restrict__ g, const float* __restrict__ beta,
    float* __restrict__ out, __nv_bfloat16* __restrict__ A2)
{
    const int row = blockIdx.x;
    const int tid = threadIdx.x;
    const float* a = A + (size_t)row * Dn;
    const float* b = Bv + (size_t)row * Dn;

    float v[4];
    float s = 0.f, s2 = 0.f;
#pragma unroll
    for (int i = 0; i < 4; i++) {
        int c = tid + i * 256;
        v[i] = a[c] + b[c];
        s += v[i];
        s2 += v[i] * v[i];
    }
#pragma unroll
    for (int off = 16; off >= 1; off >>= 1) {
        s  += __shfl_xor_sync(0xffffffffu, s,  off);
        s2 += __shfl_xor_sync(0xffffffffu, s2, off);
    }
    __shared__ float red[16];
    const int w = tid >> 5;
    if ((tid & 31) == 0) { red[w] = s; red[w + 8] = s2; }
    __syncthreads();
    float ts = 0.f, ts2 = 0.f;
#pragma unroll
    for (int i = 0; i < 8; i++) { ts += red[i]; ts2 += red[8 + i]; }
    const float mu  = ts * (1.f / Dn);
    const float var = ts2 * (1.f / Dn) - mu * mu;
    const float r = rsqrtf(var + 1e-5f);
    float* orow = out + (size_t)row * Dn;
    __nv_bfloat16* a2 = PAIR ? (A2 + (size_t)row * 2048) : nullptr;
#pragma unroll
    for (int i = 0; i < 4; i++) {
        int c = tid + i * 256;
        float y = (v[i] - mu) * r * g[c] + beta[c];
        orow[c] = y;
        if (PAIR) {
            __nv_bfloat16 hi = __float2bfloat16(y);
            __nv_bfloat16 lo = __float2bfloat16(y - __bfloat162float(hi));
            a2[c] = hi; a2[Dn + c] = lo;
        }
    }
}

// ---------------------------------------------------------------------------
extern "C" void kernel_launch(void* const* d_in, const int* in_sizes, int n_in,
                              void* d_out, int out_size)
{
    (void)in_sizes; (void)n_in; (void)out_size;
    const float* x    = (const float*)d_in[0];
    const float* Wq   = (const float*)d_in[1];
    const float* Wk   = (const float*)d_in[2];
    const float* Wv   = (const float*)d_in[3];
    const float* W1   = (const float*)d_in[4];
    const float* b1   = (const float*)d_in[5];
    const float* W2   = (const float*)d_in[6];
    const float* b2   = (const float*)d_in[7];
    const float* ln1g = (const float*)d_in[8];
    const float* ln1b = (const float*)d_in[9];
    const float* ln2g = (const float*)d_in[10];
    const float* ln2b = (const float*)d_in[11];
    float* out = (float*)d_out;

    __nv_bfloat16 *A2x, *B2qkv, *A2x1, *B2w1, *A2h, *B2w2;
    float *QKV, *att, *x1, *ff;
    cudaGetSymbolAddress((void**)&A2x,   g_A2x);
    cudaGetSymbolAddress((void**)&B2qkv, g_B2qkv);
    cudaGetSymbolAddress((void**)&QKV,   g_QKV);
    cudaGetSymbolAddress((void**)&att,   g_att);
    cudaGetSymbolAddress((void**)&x1,    g_x1);
    cudaGetSymbolAddress((void**)&A2x1,  g_A2x1);
    cudaGetSymbolAddress((void**)&B2w1,  g_B2w1);
    cudaGetSymbolAddress((void**)&A2h,   g_A2h);
    cudaGetSymbolAddress((void**)&B2w2,  g_B2w2);
    cudaGetSymbolAddress((void**)&ff,    g_ff);

    static cudaStream_t s_side = nullptr;
    static cudaEvent_t  ev_fork = nullptr, ev_join = nullptr;
    if (s_side == nullptr) {
        cudaStreamCreateWithFlags(&s_side, cudaStreamNonBlocking);
        cudaEventCreateWithFlags(&ev_fork, cudaEventDisableTiming);
        cudaEventCreateWithFlags(&ev_join, cudaEventDisableTiming);
    }

    const int GEMM_SMEM = 3 * 32768 + 128;
    const int ATT_SMEM  = 34816;
    cudaFuncSetAttribute(gemm3_kernel<0>, cudaFuncAttributeMaxDynamicSharedMemorySize, GEMM_SMEM);
    cudaFuncSetAttribute(gemm3_kernel<1>, cudaFuncAttributeMaxDynamicSharedMemorySize, GEMM_SMEM);
    cudaFuncSetAttribute(gemm3_kernel<2>, cudaFuncAttributeMaxDynamicSharedMemorySize, GEMM_SMEM);
    cudaFuncSetAttribute(attn_mma_kernel, cudaFuncAttributeMaxDynamicSharedMemorySize, ATT_SMEM);

    cudaEventRecord(ev_fork, 0);
    cudaStreamWaitEvent(s_side, ev_fork, 0);

    // submission order: conv2(1), wtrans_qkv(2), W1-side(3), gemm(4) <- ncu slot
    conv2_kernel<<<Mrows, 256>>>(x, A2x);                                        // 1
    wtrans2_qkv_kernel<<<dim3(32, 32, 3), 256>>>(Wq, Wk, Wv, B2qkv);             // 2
    wtrans2_kernel<<<dim3(DFn / 32, Dn / 32), 256, 0, s_side>>>(W1, B2w1, Dn, DFn, 2048); // 3 (side)

    // ---- QKV = x @ [Wq|Wk|Wv]  (M=4096, N=3072, K=1024) ----                  // 4
    gemm3_kernel<0><<<dim3(3072 / 128, Mrows / 128), 256, GEMM_SMEM>>>(
        A2x, B2qkv, nullptr, QKV, 3072, nullptr, 0, 0, Dn, Dn / 64);

    wtrans2_kernel<<<dim3(Dn / 32, DFn / 32), 256, 0, s_side>>>(W2, B2w2, DFn, Dn, 8192); // 5 (side)
    cudaEventRecord(ev_join, s_side);

    // ---- attention (HMMA, f16 softmax/PV, dedup smem, reg-prefetch) ----
    attn_mma_kernel<<<dim3(Tn / 128, Bsz * Hn), 256, ATT_SMEM>>>(
        QKV, QKV + 1024, QKV + 2048, att);

    // ---- x1 = LN(x + att)  (+ (hi|lo) split for FFN1) ----
    add_ln_kernel<1><<<Mrows, 256>>>(x, att, ln1g, ln1b, x1, A2x1);

    // ---- join side stream before FFN1 ----
    cudaStreamWaitEvent(0, ev_join, 0);

    // ---- h1 = relu(x1 @ W1 + b1) -> bf16 (hi|lo)  (K=1024) ----
    gemm3_kernel<1><<<dim3(DFn / 128, Mrows / 128), 256, GEMM_SMEM>>>(
        A2x1, B2w1, b1, nullptr, 0, A2h, 8192, DFn, Dn, Dn / 64);

    // ---- ff = h1 @ W2 + b2  (K=4096) ----
    gemm3_kernel<2><<<dim3(Dn / 128, Mrows / 128), 256, GEMM_SMEM>>>(
        A2h, B2w2, b2, ff, Dn, nullptr, 0, 0, DFn, DFn / 64);

    // ---- out = LN(x1 + ff) ----
    add_ln_kernel<0><<<Mrows, 256>>>(x1, ff, ln2g, ln2b, out, nullptr);
}

// round 17
// speedup vs baseline: 1.1547x; 1.0086x over previous
#include <cuda_runtime.h>
#include <cuda_bf16.h>
#include <cuda_fp16.h>
#include <cstdint>
#include <cstddef>

// ---------------------------------------------------------------------------
// EncoderStack B=4 T=1024 D=1024 H=16 DK=64 DF=4096, fp32 in/out.
// GEMMs + attention via mma.sync bf16 split-precision (K'=3K, segment-mapped
// (hi|lo) storage).  GEMM mainloop: 3-stage cp.async with the prefetch burst
// interleaved into the k-steps (tensor pipe starts ~70 cyc earlier per tile).
// Attention: f16x2 ex2 softmax, f16 PV, ones-column sums, dedup smem,
// register-prefetched K/V.  Merged QKV transpose; W1/W2 on a side stream.
// ---------------------------------------------------------------------------
#define Bsz 4
#define Tn  1024
#define Dn  1024
#define Hn  16
#define DKn 64
#define DFn 4096
#define Mrows 4096
#define LDQKV 3072

// ---- scratch (device globals; allocation-free per harness rules) ----------
__device__ __nv_bfloat16 g_A2x [Mrows * 2048];     // x  (hi|lo)
__device__ __nv_bfloat16 g_B2qkv[3072 * 2048];     // Wq|Wk|Wv^T (hi|lo)
__device__ float         g_QKV [Mrows * 3072];
__device__ float         g_att [Mrows * Dn];
__device__ float         g_x1  [Mrows * Dn];
__device__ __nv_bfloat16 g_A2x1[Mrows * 2048];     // x1 (hi|lo)
__device__ __nv_bfloat16 g_B2w1[DFn * 2048];       // W1^T (hi|lo)
__device__ __nv_bfloat16 g_A2h [Mrows * 8192];     // relu(h1) (hi|lo)
__device__ __nv_bfloat16 g_B2w2[Dn * 8192];        // W2^T (hi|lo)
__device__ float         g_ff  [Mrows * Dn];

__device__ __forceinline__ uint32_t smem_u32(const void* p) {
    uint32_t a;
    asm("{ .reg .u64 t; cvta.to.shared.u64 t, %1; cvt.u32.u64 %0, t; }"
        : "=r"(a) : "l"(p));
    return a;
}
__device__ __forceinline__ void split2(float a, float b, uint32_t& hi, uint32_t& lo) {
    __nv_bfloat16 ha = __float2bfloat16(a), hb = __float2bfloat16(b);
    __nv_bfloat16 la = __float2bfloat16(a - __bfloat162float(ha));
    __nv_bfloat16 lb = __float2bfloat16(b - __bfloat162float(hb));
    __nv_bfloat162 H; H.x = ha; H.y = hb;
    __nv_bfloat162 L; L.x = la; L.y = lb;
    hi = *(uint32_t*)&H; lo = *(uint32_t*)&L;
}

#define LDSM_X4(d, addr)                                                        \
    asm volatile("ldmatrix.sync.aligned.m8n8.x4.shared.b16 {%0,%1,%2,%3}, [%4];"\
        : "=r"((d)[0]), "=r"((d)[1]), "=r"((d)[2]), "=r"((d)[3]) : "r"(addr))
#define MMA16816(c, a0, a1, a2, a3, b0, b1)                                     \
    asm volatile("mma.sync.aligned.m16n8k16.row.col.f32.bf16.bf16.f32 "         \
        "{%0,%1,%2,%3}, {%4,%5,%6,%7}, {%8,%9}, {%0,%1,%2,%3};"                 \
        : "+f"((c)[0]), "+f"((c)[1]), "+f"((c)[2]), "+f"((c)[3])                \
        : "r"(a0), "r"(a1), "r"(a2), "r"(a3), "r"(b0), "r"(b1))
#define MMA16816F16(c, a0, a1, a2, a3, b0, b1)                                  \
    asm volatile("mma.sync.aligned.m16n8k16.row.col.f32.f16.f16.f32 "           \
        "{%0,%1,%2,%3}, {%4,%5,%6,%7}, {%8,%9}, {%0,%1,%2,%3};"                 \
        : "+f"((c)[0]), "+f"((c)[1]), "+f"((c)[2]), "+f"((c)[3])                \
        : "r"(a0), "r"(a1), "r"(a2), "r"(a3), "r"(b0), "r"(b1))

// ---------------------------------------------------------------------------
// Split-bf16 HMMA GEMM, 3-stage cp.async, prefetch interleaved into k-steps.
// A,B stored (hi|lo), row stride 2*Ksz. k-tile t in [0, 3*KT0):
//   seg = t/KT0;  A pattern (hi,hi,lo);  B pattern (hi,lo,hi).
// EPI 0: C fp32.  EPI 1: +bias, relu, (hi|lo) bf16 pair to C3.  EPI 2: +bias.
// ---------------------------------------------------------------------------
template <int EPI>
__global__ __launch_bounds__(256) void gemm3_kernel(
    const __nv_bfloat16* __restrict__ A, const __nv_bfloat16* __restrict__ B,
    const float* __restrict__ bias,
    float* __restrict__ C, int ldc,
    __nv_bfloat16* __restrict__ C3, int c3stride, int c3seg,
    int Ksz, int KT0)
{
    extern __shared__ char dynsm[];
    char* base = (char*)(((uintptr_t)dynsm + 127) & ~(uintptr_t)127);
    __shared__ float s_bias[128];

    const int tid  = threadIdx.x;
    const int wid  = tid >> 5;
    const int lane = tid & 31;
    const int bm = blockIdx.y * 128;
    const int bn = blockIdx.x * 128;
    const int K2 = 2 * Ksz;
    const int KT = 3 * KT0;

    if (EPI > 0 && tid < 128) s_bias[tid] = bias[bn + tid];

    uint32_t sA[3], sB[3];
#pragma unroll
    for (int s = 0; s < 3; s++) {
        sA[s] = smem_u32(base + s * 32768);
        sB[s] = sA[s] + 16384;
    }

    const __nv_bfloat16* Abase = A + (size_t)bm * K2;
    const __nv_bfloat16* Bbase = B + (size_t)bn * K2;

#define LOAD_STAGE(s, u)                                                        \
    do {                                                                        \
        const int _seg = ((u) >= 2 * KT0) ? 2 : (((u) >= KT0) ? 1 : 0);         \
        const int _kin = (u) - _seg * KT0;                                      \
        const __nv_bfloat16* Ag = Abase + (size_t)((_seg == 2) ? Ksz : 0)       \
                                        + (size_t)_kin * 64;                    \
        const __nv_bfloat16* Bg = Bbase + (size_t)((_seg == 1) ? Ksz : 0)       \
                                        + (size_t)_kin * 64;                    \
        _Pragma("unroll")                                                       \
        for (int i = 0; i < 4; i++) {                                           \
            int idx = tid + i * 256;                                            \
            int r = idx >> 3, ch = idx & 7;                                     \
            uint32_t off = (uint32_t)(r * 128 + ((ch ^ (r & 7)) << 4));         \
            asm volatile("cp.async.cg.shared.global [%0], [%1], 16;"            \
                :: "r"(sA[s] + off), "l"(Ag + (size_t)r * K2 + ch * 8)          \
                : "memory");                                                    \
            asm volatile("cp.async.cg.shared.global [%0], [%1], 16;"            \
                :: "r"(sB[s] + off), "l"(Bg + (size_t)r * K2 + ch * 8)          \
                : "memory");                                                    \
        }                                                                       \
        asm volatile("cp.async.commit_group;" ::: "memory");                    \
    } while (0)

    const int wm = (wid >> 2) * 64;
    const int wn = (wid & 3) * 32;
    const int a_roff = ((lane >> 3) & 1) * 8 + (lane & 7);
    const int a_koff = lane >> 4;
    const int b_roff = ((lane >> 4) & 1) * 8 + (lane & 7);
    const int b_koff = (lane >> 3) & 1;

    float acc[4][4][4];
#pragma unroll
    for (int mt = 0; mt < 4; mt++)
#pragma unroll
        for (int nt = 0; nt < 4; nt++)
#pragma unroll
            for (int e = 0; e < 4; e++) acc[mt][nt][e] = 0.f;

    LOAD_STAGE(0, 0);
    LOAD_STAGE(1, 1);

    int sidx = 0;
    for (int t = 0; t < KT; t++) {
        if (t + 1 < KT) {
            asm volatile("cp.async.wait_group 1;" ::: "memory");
        } else {
            asm volatile("cp.async.wait_group 0;" ::: "memory");
        }
        __syncthreads();

        // next-next tile's pointers (issued chunk-wise inside the k-steps)
        const int u = t + 2;
        const bool pre = (u < KT);
        const int ns = (sidx + 2 >= 3) ? sidx - 1 : sidx + 2;
        const int useg = (u >= 2 * KT0) ? 2 : ((u >= KT0) ? 1 : 0);
        const int ukin = pre ? (u - useg * KT0) : 0;
        const __nv_bfloat16* Ag = Abase + (size_t)((useg == 2) ? Ksz : 0)
                                        + (size_t)ukin * 64;
        const __nv_bfloat16* Bg = Bbase + (size_t)((useg == 1) ? Ksz : 0)
                                        + (size_t)ukin * 64;

        const uint32_t cA = sA[sidx], cB = sB[sidx];
#pragma unroll
        for (int ks = 0; ks < 4; ks++) {
            uint32_t af[4][4], bf2[2][4];
#pragma unroll
            for (int mt = 0; mt < 4; mt++) {
                int rA = wm + mt * 16 + a_roff;
                uint32_t addr = cA + rA * 128 +
                                ((((ks << 1) + a_koff) ^ (rA & 7)) << 4);
                LDSM_X4(af[mt], addr);
            }
#pragma unroll
            for (int p = 0; p < 2; p++) {
                int rB = wn + p * 16 + b_roff;
                uint32_t addr = cB + rB * 128 +
                                ((((ks << 1) + b_koff) ^ (rB & 7)) << 4);
                LDSM_X4(bf2[p], addr);
            }
            // interleaved prefetch: one chunk-pair of tile t+2 per k-step
            if (pre) {
                int idx = tid + ks * 256;
                int r = idx >> 3, ch = idx & 7;
                uint32_t off = (uint32_t)(r * 128 + ((ch ^ (r & 7)) << 4));
                asm volatile("cp.async.cg.shared.global [%0], [%1], 16;"
                    :: "r"(sA[ns] + off), "l"(Ag + (size_t)r * K2 + ch * 8)
                    : "memory");
                asm volatile("cp.async.cg.shared.global [%0], [%1], 16;"
                    :: "r"(sB[ns] + off), "l"(Bg + (size_t)r * K2 + ch * 8)
                    : "memory");
            }
#pragma unroll
            for (int mt = 0; mt < 4; mt++)
#pragma unroll
                for (int nt = 0; nt < 4; nt++) {
                    uint32_t b0 = bf2[nt >> 1][(nt & 1) * 2];
                    uint32_t b1 = bf2[nt >> 1][(nt & 1) * 2 + 1];
                    MMA16816(acc[mt][nt], af[mt][0], af[mt][1], af[mt][2], af[mt][3], b0, b1);
                }
        }
        if (pre) asm volatile("cp.async.commit_group;" ::: "memory");
        sidx = (sidx + 1 == 3) ? 0 : sidx + 1;
    }
#undef LOAD_STAGE

    const int lr = lane >> 2;
    const int lc = (lane & 3) * 2;
#pragma unroll
    for (int mt = 0; mt < 4; mt++) {
#pragma unroll
        for (int nt = 0; nt < 4; nt++) {
            float* c = acc[mt][nt];
            const int tc   = wn + nt * 8 + lc;
            const int row0 = bm + wm + mt * 16 + lr;
            if (EPI == 1) {
                float h0a = fmaxf(c[0] + s_bias[tc],     0.f);
                float h1a = fmaxf(c[1] + s_bias[tc + 1], 0.f);
                float h0b = fmaxf(c[2] + s_bias[tc],     0.f);
                float h1b = fmaxf(c[3] + s_bias[tc + 1], 0.f);
                const int nn = bn + tc;
#pragma unroll
                for (int half = 0; half < 2; half++) {
                    float v0 = half ? h0b : h0a;
                    float v1 = half ? h1b : h1a;
                    uint32_t hh, ll;
                    split2(v0, v1, hh, ll);
                    __nv_bfloat16* o = C3 + (size_t)(row0 + half * 8) * c3stride;
                    *(uint32_t*)(o + nn)         = hh;
                    *(uint32_t*)(o + c3seg + nn) = ll;
                }
            } else {
                float b0v = (EPI == 2) ? s_bias[tc]     : 0.f;
                float b1v = (EPI == 2) ? s_bias[tc + 1] : 0.f;
                float2 v0 = make_float2(c[0] + b0v, c[1] + b1v);
                float2 v1 = make_float2(c[2] + b0v, c[3] + b1v);
                *(float2*)(C + (size_t)row0 * ldc + bn + tc)       = v0;
                *(float2*)(C + (size_t)(row0 + 8) * ldc + bn + tc) = v1;
            }
        }
    }
}

// ---------------------------------------------------------------------------
// HMMA flash attention (validated R16: dedup smem, reg-prefetch, f16 softmax).
// ---------------------------------------------------------------------------
__global__ __launch_bounds__(256) void attn_mma_kernel(
    const float* __restrict__ Qg, const float* __restrict__ Kg,
    const float* __restrict__ Vg, float* __restrict__ Og)
{
    extern __shared__ char smraw[];
    char* smp = smraw;
    const uint32_t sQ = smem_u32(smraw);
    const uint32_t sK = sQ;
    const uint32_t sV = sQ + 17408;

    const int tid = threadIdx.x;
    const int wid = tid >> 5, lane = tid & 31;
    const int bh = blockIdx.y;
    const int b = bh >> 4, h = bh & 15;
    const int q0 = blockIdx.x * 128;
    const float* Qbase = Qg + (size_t)b * Tn * LDQKV + h * DKn;
    const float* Kbase = Kg + (size_t)b * Tn * LDQKV + h * DKn;
    const float* Vbase = Vg + (size_t)b * Tn * LDQKV + h * DKn;
    float* Obase = Og + (size_t)b * Tn * Dn + h * DKn;

    const int a_roff = ((lane >> 3) & 1) * 8 + (lane & 7);
    const int a_koff = lane >> 4;
    const int b_roff = ((lane >> 4) & 1) * 8 + (lane & 7);
    const int b_koff = (lane >> 3) & 1;

    const int QOFF[12] = {0,32,64,96, 0,32,64,96, 128,160,192,224};
    const int KOFF[12] = {0,32,64,96, 128,160,192,224, 0,32,64,96};

#pragma unroll
    for (int i = 0; i < 8; i++) {
        int idx = tid + i * 256;
        int r = idx >> 4, c4 = (idx & 15) * 4;
        float4 q = *(const float4*)(Qbase + (size_t)(q0 + r) * LDQKV + c4);
        q.x *= 0.125f; q.y *= 0.125f; q.z *= 0.125f; q.w *= 0.125f;
        uint32_t h0, l0, h1, l1;
        split2(q.x, q.y, h0, l0);
        split2(q.z, q.w, h1, l1);
        char* row = smp + r * 272;
        *(uint2*)(row + c4 * 2)       = make_uint2(h0, h1);
        *(uint2*)(row + 128 + c4 * 2) = make_uint2(l0, l1);
    }
    __syncthreads();

    uint32_t qf[12][4];
#pragma unroll
    for (int kt = 0; kt < 12; kt++) {
        uint32_t addr = sQ + (wid * 16 + a_roff) * 272 + QOFF[kt] + a_koff * 16;
        LDSM_X4(qf[kt], addr);
    }
    __syncthreads();

    float m0 = -1e30f, m1 = -1e30f;
    float of[8][4], osum[4];
#pragma unroll
    for (int j = 0; j < 8; j++)
#pragma unroll
        for (int e = 0; e < 4; e++) of[j][e] = 0.f;
#pragma unroll
    for (int e = 0; e < 4; e++) osum[e] = 0.f;

    const uint32_t ONES_H2 = 0x3C003C00u;
    const float L2E = 1.4426950408889634f;

    const int pr = tid >> 4;
    const int pc4 = (tid & 15) * 4;

    float4 kreg[4], vreg[4];
#pragma unroll
    for (int i = 0; i < 4; i++) {
        int r = pr + i * 16;
        kreg[i] = *(const float4*)(Kbase + (size_t)r * LDQKV + pc4);
        vreg[i] = *(const float4*)(Vbase + (size_t)r * LDQKV + pc4);
    }

    for (int kv0 = 0; kv0 < Tn; kv0 += 64) {
#pragma unroll
        for (int i = 0; i < 4; i++) {
            int r = pr + i * 16;
            uint32_t h0, lo0, h1, lo1;
            split2(kreg[i].x, kreg[i].y, h0, lo0);
            split2(kreg[i].z, kreg[i].w, h1, lo1);
            char* row = smp + r * 272;
            *(uint2*)(row + pc4 * 2)       = make_uint2(h0, h1);
            *(uint2*)(row + 128 + pc4 * 2) = make_uint2(lo0, lo1);

            char* vb = smp + 17408 + r * 2;
            *(__half*)(vb + (pc4 + 0) * 144) = __float2half(vreg[i].x);
            *(__half*)(vb + (pc4 + 1) * 144) = __float2half(vreg[i].y);
            *(__half*)(vb + (pc4 + 2) * 144) = __float2half(vreg[i].z);
            *(__half*)(vb + (pc4 + 3) * 144) = __float2half(vreg[i].w);
        }
        __syncthreads();

        if (kv0 + 64 < Tn) {
            const int nkv = kv0 + 64;
#pragma unroll
            for (int i = 0; i < 4; i++) {
                int r = nkv + pr + i * 16;
                kreg[i] = *(const float4*)(Kbase + (size_t)r * LDQKV + pc4);
                vreg[i] = *(const float4*)(Vbase + (size_t)r * LDQKV + pc4);
            }
        }

        float sf[8][4];
#pragma unroll
        for (int nt = 0; nt < 8; nt++)
#pragma unroll
            for (int e = 0; e < 4; e++) sf[nt][e] = 0.f;

#pragma unroll
        for (int kt = 0; kt < 12; kt++) {
            uint32_t bf[4][4];
#pragma unroll
            for (int p = 0; p < 4; p++) {
                uint32_t addr = sK + (p * 16 + b_roff) * 272 + KOFF[kt] + b_koff * 16;
                LDSM_X4(bf[p], addr);
            }
#pragma unroll
            for (int nt = 0; nt < 8; nt++) {
                uint32_t bb0 = bf[nt >> 1][(nt & 1) * 2];
                uint32_t bb1 = bf[nt >> 1][(nt & 1) * 2 + 1];
                MMA16816(sf[nt], qf[kt][0], qf[kt][1], qf[kt][2], qf[kt][3], bb0, bb1);
            }
        }

        float mx0 = -1e30f, mx1 = -1e30f;
#pragma unroll
        for (int nt = 0; nt < 8; nt++) {
            mx0 = fmaxf(mx0, fmaxf(sf[nt][0], sf[nt][1]));
            mx1 = fmaxf(mx1, fmaxf(sf[nt][2], sf[nt][3]));
        }
        mx0 = fmaxf(mx0, __shfl_xor_sync(0xffffffffu, mx0, 1));
        mx0 = fmaxf(mx0, __shfl_xor_sync(0xffffffffu, mx0, 2));
        mx1 = fmaxf(mx1, __shfl_xor_sync(0xffffffffu, mx1, 1));
        mx1 = fmaxf(mx1, __shfl_xor_sync(0xffffffffu, mx1, 2));
        float mn0 = fmaxf(m0, mx0), mn1 = fmaxf(m1, mx1);
        float alpha0 = __expf(m0 - mn0), alpha1 = __expf(m1 - mn1);
        m0 = mn0; m1 = mn1;

        const float nb0 = mn0 * L2E, nb1 = mn1 * L2E;
        uint32_t hp[8][2];
#pragma unroll
        for (int nt = 0; nt < 8; nt++) {
            float t0 = fmaf(sf[nt][0], L2E, -nb0);
            float t1 = fmaf(sf[nt][1], L2E, -nb0);
            float t2 = fmaf(sf[nt][2], L2E, -nb1);
            float t3 = fmaf(sf[nt][3], L2E, -nb1);
            __half2 h01 = h2exp2(__floats2half2_rn(t0, t1));
            __half2 h23 = h2exp2(__floats2half2_rn(t2, t3));
            hp[nt][0] = *(uint32_t*)&h01;
            hp[nt][1] = *(uint32_t*)&h23;
        }

#pragma unroll
        for (int j = 0; j < 8; j++) {
            of[j][0] *= alpha0; of[j][1] *= alpha0;
            of[j][2] *= alpha1; of[j][3] *= alpha1;
        }
        osum[0] *= alpha0; osum[1] *= alpha0;
        osum[2] *= alpha1; osum[3] *= alpha1;

#pragma unroll
        for (int g = 0; g < 4; g++) {
            uint32_t a0 = hp[2 * g][0];
            uint32_t a1 = hp[2 * g][1];
            uint32_t a2 = hp[2 * g + 1][0];
            uint32_t a3 = hp[2 * g + 1][1];
            uint32_t vf[4][4];
#pragma unroll
            for (int p = 0; p < 4; p++) {
                uint32_t addr = sV + (p * 16 + b_roff) * 144 + (g * 2 + b_koff) * 16;
                LDSM_X4(vf[p], addr);
            }
#pragma unroll
            for (int j = 0; j < 8; j++) {
                uint32_t bb0 = vf[j >> 1][(j & 1) * 2];
                uint32_t bb1 = vf[j >> 1][(j & 1) * 2 + 1];
                MMA16816F16(of[j], a0, a1, a2, a3, bb0, bb1);
            }
            MMA16816F16(osum, a0, a1, a2, a3, ONES_H2, ONES_H2);
        }
        __syncthreads();
    }

    const float inv0 = 1.f / osum[0], inv1 = 1.f / osum[2];
    const int r0 = q0 + wid * 16 + (lane >> 2);
    const int cc = (lane & 3) * 2;
#pragma unroll
    for (int j = 0; j < 8; j++) {
        *(float2*)(Obase + (size_t)r0 * Dn + j * 8 + cc) =
            make_float2(of[j][0] * inv0, of[j][1] * inv0);
        *(float2*)(Obase + (size_t)(r0 + 8) * Dn + j * 8 + cc) =
            make_float2(of[j][2] * inv1, of[j][3] * inv1);
    }
}

// ---------------------------------------------------------------------------
// Weight transpose + split:  W[K,N] fp32  ->  B2[N, 2K] bf16 = (hi | lo)
// ---------------------------------------------------------------------------
__global__ __launch_bounds__(256) void wtrans2_kernel(
    const float* __restrict__ W, __nv_bfloat16* __restrict__ B2,
    int K, int N, int K2)
{
    __shared__ float t[32][33];
    const int n0 = blockIdx.x * 32, k0 = blockIdx.y * 32;
    const int tx = threadIdx.x & 31, ty = threadIdx.x >> 5;
#pragma unroll
    for (int i = 0; i < 4; i++)
        t[ty + 8 * i][tx] = W[(size_t)(k0 + ty + 8 * i) * N + n0 + tx];
    __syncthreads();
#pragma unroll
    for (int i = 0; i < 4; i++) {
        int n = n0 + ty + 8 * i;
        int k = k0 + tx;
        float v = t[tx][ty + 8 * i];
        __nv_bfloat16 hi = __float2bfloat16(v);
        __nv_bfloat16 lo = __float2bfloat16(v - __bfloat162float(hi));
        __nv_bfloat16* row = B2 + (size_t)n * K2;
        row[k] = hi; row[K + k] = lo;
    }
}

// Merged Wq/Wk/Wv transpose (grid.z selects matrix) -> B2qkv rows z*1024..
__global__ __launch_bounds__(256) void wtrans2_qkv_kernel(
    const float* __restrict__ Wq, const float* __restrict__ Wk,
    const float* __restrict__ Wv, __nv_bfloat16* __restrict__ B2)
{
    const float* W = (blockIdx.z == 0) ? Wq : (blockIdx.z == 1) ? Wk : Wv;
    __nv_bfloat16* B2z = B2 + (size_t)blockIdx.z * 1024 * 2048;
    __shared__ float t[32][33];
    const int n0 = blockIdx.x * 32, k0 = blockIdx.y * 32;
    const int tx = threadIdx.x & 31, ty = threadIdx.x >> 5;
#pragma unroll
    for (int i = 0; i < 4; i++)
        t[ty + 8 * i][tx] = W[(size_t)(k0 + ty + 8 * i) * 1024 + n0 + tx];
    __syncthreads();
#pragma unroll
    for (int i = 0; i < 4; i++) {
        int n = n0 + ty + 8 * i;
        int k = k0 + tx;
        float v = t[tx][ty + 8 * i];
        __nv_bfloat16 hi = __float2bfloat16(v);
        __nv_bfloat16 lo = __float2bfloat16(v - __bfloat162float(hi));
        __nv_bfloat16* row = B2z + (size_t)n * 2048;
        row[k] = hi; row[1024 + k] = lo;
    }
}

// x fp32 [4096,1024] -> A2 bf16 [4096, 2048] = (hi | lo)
__global__ __launch_bounds__(256) void conv2_kernel(
    const float* __restrict__ X, __nv_bfloat16* __restrict__ A2)
{
    const int m = blockIdx.x;
    const float* xr = X + (size_t)m * Dn;
    __nv_bfloat16* ar = A2 + (size_t)m * 2048;
#pragma unroll
    for (int i = 0; i < 4; i++) {
        int k = threadIdx.x + i * 256;
        float v = xr[k];
        __nv_bfloat16 hi = __float2bfloat16(v);
        __nv_bfloat16 lo = __float2bfloat16(v - __bfloat162float(hi));
        ar[k] = hi; ar[Dn + k] = lo;
    }
}

// ---------------------------------------------------------------------------
// LayerNorm(a+b)*g+beta.  PAIR=1 also writes the (hi|lo) bf16 split.
// ---------------------------------------------------------------------------
template <int PAIR>
__global__ __launch_bounds__(256) void add_ln_kernel(
    const float* __restrict__ A, const float* __restrict__ Bv,
    const float* __restrict__ g, const float* __restrict__ beta,
    float* __restrict__ out, __nv_bfloat16* __restrict__ A2)
{
    const int row = blockIdx.x;
    const int tid = threadIdx.x;
    const float* a = A + (size_t)row * Dn;
    const float* b = Bv + (size_t)row * Dn;

    float v[4];
    float s = 0.f, s2 = 0.f;
#pragma unroll
    for (int i = 0; i < 4; i++) {
        int c = tid + i * 256;
        v[i] = a[c] + b[c];
        s += v[i];
        s2 += v[i] * v[i];
    }
#pragma unroll
    for (int off = 16; off >= 1; off >>= 1) {
        s  += __shfl_xor_sync(0xffffffffu, s,  off);
        s2 += __shfl_xor_sync(0xffffffffu, s2, off);
    }
    __shared__ float red[16];
    const int w = tid >> 5;
    if ((tid & 31) == 0) { red[w] = s; red[w + 8] = s2; }
    __syncthreads();
    float ts = 0.f, ts2 = 0.f;
#pragma unroll
    for (int i = 0; i < 8; i++) { ts += red[i]; ts2 += red[8 + i]; }
    const float mu  = ts * (1.f / Dn);
    const float var = ts2 * (1.f / Dn) - mu * mu;
    const float r = rsqrtf(var + 1e-5f);
    float* orow = out + (size_t)row * Dn;
    __nv_bfloat16* a2 = PAIR ? (A2 + (size_t)row * 2048) : nullptr;
#pragma unroll
    for (int i = 0; i < 4; i++) {
        int c = tid + i * 256;
        float y = (v[i] - mu) * r * g[c] + beta[c];
        orow[c] = y;
        if (PAIR) {
            __nv_bfloat16 hi = __float2bfloat16(y);
            __nv_bfloat16 lo = __float2bfloat16(y - __bfloat162float(hi));
            a2[c] = hi; a2[Dn + c] = lo;
        }
    }
}

// ---------------------------------------------------------------------------
extern "C" void kernel_launch(void* const* d_in, const int* in_sizes, int n_in,
                              void* d_out, int out_size)
{
    (void)in_sizes; (void)n_in; (void)out_size;
    const float* x    = (const float*)d_in[0];
    const float* Wq   = (const float*)d_in[1];
    const float* Wk   = (const float*)d_in[2];
    const float* Wv   = (const float*)d_in[3];
    const float* W1   = (const float*)d_in[4];
    const float* b1   = (const float*)d_in[5];
    const float* W2   = (const float*)d_in[6];
    const float* b2   = (const float*)d_in[7];
    const float* ln1g = (const float*)d_in[8];
    const float* ln1b = (const float*)d_in[9];
    const float* ln2g = (const float*)d_in[10];
    const float* ln2b = (const float*)d_in[11];
    float* out = (float*)d_out;

    __nv_bfloat16 *A2x, *B2qkv, *A2x1, *B2w1, *A2h, *B2w2;
    float *QKV, *att, *x1, *ff;
    cudaGetSymbolAddress((void**)&A2x,   g_A2x);
    cudaGetSymbolAddress((void**)&B2qkv, g_B2qkv);
    cudaGetSymbolAddress((void**)&QKV,   g_QKV);
    cudaGetSymbolAddress((void**)&att,   g_att);
    cudaGetSymbolAddress((void**)&x1,    g_x1);
    cudaGetSymbolAddress((void**)&A2x1,  g_A2x1);
    cudaGetSymbolAddress((void**)&B2w1,  g_B2w1);
    cudaGetSymbolAddress((void**)&A2h,   g_A2h);
    cudaGetSymbolAddress((void**)&B2w2,  g_B2w2);
    cudaGetSymbolAddress((void**)&ff,    g_ff);

    static cudaStream_t s_side = nullptr;
    static cudaEvent_t  ev_fork = nullptr, ev_join = nullptr;
    if (s_side == nullptr) {
        cudaStreamCreateWithFlags(&s_side, cudaStreamNonBlocking);
        cudaEventCreateWithFlags(&ev_fork, cudaEventDisableTiming);
        cudaEventCreateWithFlags(&ev_join, cudaEventDisableTiming);
    }

    const int GEMM_SMEM = 3 * 32768 + 128;
    const int ATT_SMEM  = 34816;
    cudaFuncSetAttribute(gemm3_kernel<0>, cudaFuncAttributeMaxDynamicSharedMemorySize, GEMM_SMEM);
    cudaFuncSetAttribute(gemm3_kernel<1>, cudaFuncAttributeMaxDynamicSharedMemorySize, GEMM_SMEM);
    cudaFuncSetAttribute(gemm3_kernel<2>, cudaFuncAttributeMaxDynamicSharedMemorySize, GEMM_SMEM);
    cudaFuncSetAttribute(attn_mma_kernel, cudaFuncAttributeMaxDynamicSharedMemorySize, ATT_SMEM);

    cudaEventRecord(ev_fork, 0);
    cudaStreamWaitEvent(s_side, ev_fork, 0);

    // submission order: conv2(1), wtrans_qkv(2), W1-side(3), gemm(4) <- ncu slot
    conv2_kernel<<<Mrows, 256>>>(x, A2x);                                        // 1
    wtrans2_qkv_kernel<<<dim3(32, 32, 3), 256>>>(Wq, Wk, Wv, B2qkv);             // 2
    wtrans2_kernel<<<dim3(DFn / 32, Dn / 32), 256, 0, s_side>>>(W1, B2w1, Dn, DFn, 2048); // 3 (side)

    // ---- QKV = x @ [Wq|Wk|Wv]  (M=4096, N=3072, K=1024) ----                  // 4
    gemm3_kernel<0><<<dim3(3072 / 128, Mrows / 128), 256, GEMM_SMEM>>>(
        A2x, B2qkv, nullptr, QKV, 3072, nullptr, 0, 0, Dn, Dn / 64);

    wtrans2_kernel<<<dim3(Dn / 32, DFn / 32), 256, 0, s_side>>>(W2, B2w2, DFn, Dn, 8192); // 5 (side)
    cudaEventRecord(ev_join, s_side);

    // ---- attention ----
    attn_mma_kernel<<<dim3(Tn / 128, Bsz * Hn), 256, ATT_SMEM>>>(
        QKV, QKV + 1024, QKV + 2048, att);

    // ---- x1 = LN(x + att)  (+ (hi|lo) split for FFN1) ----
    add_ln_kernel<1><<<Mrows, 256>>>(x, att, ln1g, ln1b, x1, A2x1);

    // ---- join side stream before FFN1 ----
    cudaStreamWaitEvent(0, ev_join, 0);

    // ---- h1 = relu(x1 @ W1 + b1) -> bf16 (hi|lo)  (K=1024) ----
    gemm3_kernel<1><<<dim3(DFn / 128, Mrows / 128), 256, GEMM_SMEM>>>(
        A2x1, B2w1, b1, nullptr, 0, A2h, 8192, DFn, Dn, Dn / 64);

    // ---- ff = h1 @ W2 + b2  (K=4096) ----
    gemm3_kernel<2><<<dim3(Dn / 128, Mrows / 128), 256, GEMM_SMEM>>>(
        A2h, B2w2, b2, ff, Dn, nullptr, 0, 0, DFn, DFn / 64);

    // ---- out = LN(x1 + ff) ----
    add_ln_kernel<0><<<Mrows, 256>>>(x1, ff, ln2g, ln2b, out, nullptr);
}